// round 6
// baseline (speedup 1.0000x reference)
#include <cuda_runtime.h>
#include <cuda_bf16.h>
#include <stdint.h>
#include <math.h>

#define BB 4
#define CC 256
#define HH 64
#define WW 64
#define NN (HH*WW)      // 4096
#define CQK 32

// ---- scratch (static device globals; no allocation) ----
__device__ float g_Q[BB*NN*CQK];          // 2 MB   Q^T: [b][n][d]
__device__ float g_K[BB*NN*CQK];          // 2 MB   K^T: [b][n][d]
__device__ float g_V[BB*CC*NN];           // 16 MB  [b][c][n]
__device__ float g_Linv[BB*NN];           // 1/column-sum (per k)

// ============================================================
// helpers
// ============================================================
__device__ __forceinline__ uint32_t smem_u32(const void* p) {
    uint32_t a;
    asm("{ .reg .u64 t; cvta.to.shared.u64 t, %1; cvt.u32.u64 %0, t; }"
        : "=r"(a) : "l"(p));
    return a;
}
#define SWZ(x) ((x) ^ (((x) >> 3) & 0x70))
#define STS128U(addr, a, b, c, d) \
    asm volatile("st.shared.v4.b32 [%0], {%1, %2, %3, %4};" \
                 :: "r"(addr), "r"(a), "r"(b), "r"(c), "r"(d) : "memory")
#define STS32U(addr, a) \
    asm volatile("st.shared.b32 [%0], %1;" :: "r"(addr), "r"(a) : "memory")
#define LDMX4(r0, r1, r2, r3, a) \
    asm volatile("ldmatrix.sync.aligned.m8n8.x4.shared.b16 {%0,%1,%2,%3}, [%4];" \
                 : "=r"(r0), "=r"(r1), "=r"(r2), "=r"(r3) : "r"(a))
#define MMA16816(d, a0, a1, a2, a3, b0, b1) \
    asm volatile("mma.sync.aligned.m16n8k16.row.col.f32.bf16.bf16.f32 " \
                 "{%0,%1,%2,%3}, {%4,%5,%6,%7}, {%8,%9}, {%0,%1,%2,%3};" \
                 : "+f"((d)[0]), "+f"((d)[1]), "+f"((d)[2]), "+f"((d)[3]) \
                 : "r"(a0), "r"(a1), "r"(a2), "r"(a3), "r"(b0), "r"(b1))

__device__ __forceinline__ uint32_t pack_bf16(float a, float b) {
    __nv_bfloat162 h = __floats2bfloat162_rn(a, b);
    return *(uint32_t*)&h;
}
// split 8 floats into bf16 hi + residual lo, packed as 4+4 b32
__device__ __forceinline__ void hilo_pack8(const float4& a0, const float4& a1,
                                           uint32_t* h, uint32_t* l) {
    float v[8] = {a0.x, a0.y, a0.z, a0.w, a1.x, a1.y, a1.z, a1.w};
#pragma unroll
    for (int p = 0; p < 4; p++) {
        __nv_bfloat162 hh = __floats2bfloat162_rn(v[2*p], v[2*p+1]);
        float2 hf = __bfloat1622float2(hh);
        __nv_bfloat162 ll = __floats2bfloat162_rn(v[2*p] - hf.x, v[2*p+1] - hf.y);
        h[p] = *(uint32_t*)&hh;
        l[p] = *(uint32_t*)&ll;
    }
}

// ============================================================
// Conv 3x3 SAME: tile 32x16 spatial, block (32,8), 2 rows/thread
// trans=0: out[b][co][n] ; trans=1: out[b][n][co] (CO==32 assumed usable)
// ============================================================
#define CI_T 4
#define CO_T 8

__global__ void __launch_bounds__(256) conv3x3_kernel(
    const float* __restrict__ x, const float* __restrict__ w,
    const float* __restrict__ bias, float* __restrict__ out, int CO, int trans)
{
    __shared__ float xs[CI_T][18][34];
    __shared__ float ws[CO_T][CI_T][9];

    const int tx = threadIdx.x;            // 0..31
    const int ty = threadIdx.y;            // 0..7
    const int tid = ty * 32 + tx;
    const int tile_x = blockIdx.x * 32;
    const int tile_y = blockIdx.y * 16;
    const int cogs = CO / CO_T;
    const int cog = blockIdx.z % cogs;
    const int b   = blockIdx.z / cogs;
    const int co0 = cog * CO_T;

    float acc[CO_T][2];
#pragma unroll
    for (int i = 0; i < CO_T; i++) { acc[i][0] = 0.f; acc[i][1] = 0.f; }

    const float* xb = x + (size_t)b * CC * HH * WW;

    for (int ci0 = 0; ci0 < CC; ci0 += CI_T) {
        for (int idx = tid; idx < CI_T * 18 * 34; idx += 256) {
            int ci = idx / (18 * 34);
            int rr = (idx / 34) % 18;
            int cc = idx % 34;
            int gy = tile_y + rr - 1;
            int gx = tile_x + cc - 1;
            float v = 0.f;
            if (gy >= 0 && gy < HH && gx >= 0 && gx < WW)
                v = xb[(size_t)(ci0 + ci) * HH * WW + gy * WW + gx];
            xs[ci][rr][cc] = v;
        }
        for (int idx = tid; idx < CO_T * CI_T * 9; idx += 256) {
            int co = idx / (CI_T * 9);
            int rem = idx % (CI_T * 9);
            int ci = rem / 9;
            int t = rem % 9;
            ws[co][ci][t] = w[((size_t)(co0 + co) * CC + (ci0 + ci)) * 9 + t];
        }
        __syncthreads();

        const int oy = ty * 2;
#pragma unroll
        for (int ci = 0; ci < CI_T; ci++) {
            float xv[4][3];
#pragma unroll
            for (int rr = 0; rr < 4; rr++)
#pragma unroll
                for (int c2 = 0; c2 < 3; c2++)
                    xv[rr][c2] = xs[ci][oy + rr][tx + c2];
#pragma unroll
            for (int co = 0; co < CO_T; co++) {
#pragma unroll
                for (int t = 0; t < 9; t++) {
                    const int dy = t / 3, dx = t % 3;
                    const float wv = ws[co][ci][t];
                    acc[co][0] = fmaf(xv[0 + dy][dx], wv, acc[co][0]);
                    acc[co][1] = fmaf(xv[1 + dy][dx], wv, acc[co][1]);
                }
            }
        }
        __syncthreads();
    }

    float bs[CO_T];
#pragma unroll
    for (int co = 0; co < CO_T; co++) bs[co] = bias[co0 + co];

    if (trans) {
#pragma unroll
        for (int r = 0; r < 2; r++) {
            const int gy = tile_y + ty * 2 + r;
            const int n = gy * WW + tile_x + tx;
            float4 f0, f1;
            f0.x = acc[0][r] + bs[0]; f0.y = acc[1][r] + bs[1];
            f0.z = acc[2][r] + bs[2]; f0.w = acc[3][r] + bs[3];
            f1.x = acc[4][r] + bs[4]; f1.y = acc[5][r] + bs[5];
            f1.z = acc[6][r] + bs[6]; f1.w = acc[7][r] + bs[7];
            *(float4*)&out[((size_t)b * NN + n) * CQK + co0]     = f0;
            *(float4*)&out[((size_t)b * NN + n) * CQK + co0 + 4] = f1;
        }
    } else {
#pragma unroll
        for (int co = 0; co < CO_T; co++) {
#pragma unroll
            for (int r = 0; r < 2; r++) {
                const int gy = tile_y + ty * 2 + r;
                const int gx = tile_x + tx;
                out[((size_t)b * CO + co0 + co) * HH * WW + gy * WW + gx] =
                    acc[co][r] + bs[co];
            }
        }
    }
}

// ============================================================
// stats: L[k] = sum_q exp(S[k,q]), S = K^T Q recomputed via mma.
// k-tile 128 (8 warps x 16 rows), q-chunks of 64.
// S via bf16 hi/lo 3-chain (KhQh + KhQl + KlQh), fp32 accum.
// ============================================================
__global__ void __launch_bounds__(256) stats_kernel()
{
    __shared__ __align__(128) uint8_t sK[128 * 128];   // [k][hi d0..31 | lo d0..31]
    __shared__ __align__(128) uint8_t sQ[64 * 128];    // [q][hi | lo]

    const int tid = threadIdx.x, wid = tid >> 5, lid = tid & 31;
    const int k0 = blockIdx.x * 128;
    const int b  = blockIdx.y;

    const uint32_t kb = smem_u32(sK);
    const uint32_t qb = smem_u32(sQ);

    // stage K tile (128 rows x 32 d), hi/lo
    {
        const float* Kg = g_K + ((size_t)b * NN + k0) * CQK;
#pragma unroll
        for (int p = 0; p < 2; p++) {
            const int r = (tid >> 2) + p * 64;
            const int f8 = (tid & 3) * 8;
            const float4 a0 = *(const float4*)&Kg[(size_t)r * CQK + f8];
            const float4 a1 = *(const float4*)&Kg[(size_t)r * CQK + f8 + 4];
            uint32_t h[4], l[4];
            hilo_pack8(a0, a1, h, l);
            STS128U(kb + SWZ((uint32_t)(r * 128 + (tid & 3) * 16)),
                    h[0], h[1], h[2], h[3]);
            STS128U(kb + SWZ((uint32_t)(r * 128 + 64 + (tid & 3) * 16)),
                    l[0], l[1], l[2], l[3]);
        }
    }

    const float* Qg = g_Q + (size_t)b * NN * CQK;
    const int qr = tid >> 2;             // 0..63
    const int qf8 = (tid & 3) * 8;

    float4 qpre0 = *(const float4*)&Qg[(size_t)qr * CQK + qf8];
    float4 qpre1 = *(const float4*)&Qg[(size_t)qr * CQK + qf8 + 4];

    const int frow = lid & 15;
    const int fhc = (lid >> 4) * 16;
    const int er = lid >> 2;

    float l0 = 0.f, l1 = 0.f;

    for (int cn = 0; cn < NN / 64; cn++) {
        __syncthreads();   // prior mma done reading sQ (and K staged, 1st iter)
        {
            uint32_t h[4], l[4];
            hilo_pack8(qpre0, qpre1, h, l);
            STS128U(qb + SWZ((uint32_t)(qr * 128 + (tid & 3) * 16)),
                    h[0], h[1], h[2], h[3]);
            STS128U(qb + SWZ((uint32_t)(qr * 128 + 64 + (tid & 3) * 16)),
                    l[0], l[1], l[2], l[3]);
        }
        __syncthreads();

        if (cn + 1 < NN / 64) {
            const size_t base = (size_t)((cn + 1) * 64 + qr) * CQK + qf8;
            qpre0 = *(const float4*)&Qg[base];
            qpre1 = *(const float4*)&Qg[base + 4];
        }

        float sa[8][4];
#pragma unroll
        for (int i = 0; i < 8; i++)
#pragma unroll
            for (int j = 0; j < 4; j++) sa[i][j] = 0.f;

#pragma unroll
        for (int s = 0; s < 2; s++) {
            uint32_t Ah[4], Al[4];
            LDMX4(Ah[0], Ah[1], Ah[2], Ah[3],
                  kb + SWZ((uint32_t)((wid * 16 + frow) * 128 + s * 32 + fhc)));
            LDMX4(Al[0], Al[1], Al[2], Al[3],
                  kb + SWZ((uint32_t)((wid * 16 + frow) * 128 + 64 + s * 32 + fhc)));
#pragma unroll
            for (int qg = 0; qg < 4; qg++) {
                uint32_t Bh[4], Bl[4];
                LDMX4(Bh[0], Bh[1], Bh[2], Bh[3],
                      qb + SWZ((uint32_t)((qg * 16 + frow) * 128 + s * 32 + fhc)));
                LDMX4(Bl[0], Bl[1], Bl[2], Bl[3],
                      qb + SWZ((uint32_t)((qg * 16 + frow) * 128 + 64 + s * 32 + fhc)));
                MMA16816(sa[qg*2+0], Ah[0], Ah[1], Ah[2], Ah[3], Bh[0], Bh[2]);
                MMA16816(sa[qg*2+1], Ah[0], Ah[1], Ah[2], Ah[3], Bh[1], Bh[3]);
                MMA16816(sa[qg*2+0], Ah[0], Ah[1], Ah[2], Ah[3], Bl[0], Bl[2]);
                MMA16816(sa[qg*2+1], Ah[0], Ah[1], Ah[2], Ah[3], Bl[1], Bl[3]);
                MMA16816(sa[qg*2+0], Al[0], Al[1], Al[2], Al[3], Bh[0], Bh[2]);
                MMA16816(sa[qg*2+1], Al[0], Al[1], Al[2], Al[3], Bh[1], Bh[3]);
            }
        }

#pragma unroll
        for (int n8 = 0; n8 < 8; n8++) {
            l0 += __expf(sa[n8][0]) + __expf(sa[n8][1]);
            l1 += __expf(sa[n8][2]) + __expf(sa[n8][3]);
        }
    }

    // reduce over the 4 lanes sharing a row
    l0 += __shfl_xor_sync(0xFFFFFFFF, l0, 1);
    l0 += __shfl_xor_sync(0xFFFFFFFF, l0, 2);
    l1 += __shfl_xor_sync(0xFFFFFFFF, l1, 1);
    l1 += __shfl_xor_sync(0xFFFFFFFF, l1, 2);
    if ((lid & 3) == 0) {
        g_Linv[b * NN + k0 + wid * 16 + er]     = 1.f / l0;
        g_Linv[b * NN + k0 + wid * 16 + er + 8] = 1.f / l1;
    }
}

// ============================================================
// fused OV: D[c,k] = sum_q V[c,q]*exp(S[k,q]) ; out = x + g*Linv[k]*D
// Block tile: c 128 x k 64; q-chunks of 64. S recomputed per chunk.
// ============================================================
__global__ void __launch_bounds__(256) fused_ov_kernel(
    const float* __restrict__ x, const float* __restrict__ gamma,
    float* __restrict__ out)
{
    __shared__ __align__(128) uint8_t sK[64 * 128];    // [k][hi|lo]
    __shared__ __align__(128) uint8_t sQ[64 * 128];    // [q][hi|lo]
    __shared__ __align__(128) uint8_t sV[128 * 128];   // [c][64 q bf16]
    __shared__ __align__(128) uint8_t sP[64 * 128];    // [k][64 q bf16]
    __shared__ float sLinv[64];

    const int tid = threadIdx.x, wid = tid >> 5, lid = tid & 31;
    const int k0 = blockIdx.x * 64;
    const int c0 = blockIdx.y * 128;
    const int b  = blockIdx.z;

    const uint32_t kb = smem_u32(sK);
    const uint32_t qb = smem_u32(sQ);
    const uint32_t vb = smem_u32(sV);
    const uint32_t pb = smem_u32(sP);

    if (tid < 64) sLinv[tid] = g_Linv[b * NN + k0 + tid];

    // stage K tile (64 rows) hi/lo — once
    {
        const float* Kg = g_K + ((size_t)b * NN + k0) * CQK;
        const int r = tid >> 2;
        const int f8 = (tid & 3) * 8;
        const float4 a0 = *(const float4*)&Kg[(size_t)r * CQK + f8];
        const float4 a1 = *(const float4*)&Kg[(size_t)r * CQK + f8 + 4];
        uint32_t h[4], l[4];
        hilo_pack8(a0, a1, h, l);
        STS128U(kb + SWZ((uint32_t)(r * 128 + (tid & 3) * 16)),
                h[0], h[1], h[2], h[3]);
        STS128U(kb + SWZ((uint32_t)(r * 128 + 64 + (tid & 3) * 16)),
                l[0], l[1], l[2], l[3]);
    }

    const float* Qg = g_Q + (size_t)b * NN * CQK;
    const float* Vg = g_V + ((size_t)b * CC + c0) * NN;

    const int qr = tid >> 2;              // 0..63 (Q stage row)
    const int qf8 = (tid & 3) * 8;
    const int vrow = tid >> 1;            // 0..127 (V stage row)
    const int vqo = (tid & 1) * 32;       // q offset

    float4 qpre0 = *(const float4*)&Qg[(size_t)qr * CQK + qf8];
    float4 qpre1 = *(const float4*)&Qg[(size_t)qr * CQK + qf8 + 4];
    float4 vpre[8];
#pragma unroll
    for (int j = 0; j < 8; j++)
        vpre[j] = *(const float4*)&Vg[(size_t)vrow * NN + vqo + j * 4];

    const int frow = lid & 15;
    const int fhc = (lid >> 4) * 16;
    const int er = lid >> 2;
    const int ec = (lid & 3) * 2;
    // S warps: swm = k16 group, swq = q32 half
    const int swm = wid & 3;
    const int swq = wid >> 2;
    // OV warps: wm = c32 group, wn = k32 half
    const int wm = wid >> 1;
    const int wn = wid & 1;

    float acc[2][4][4];
#pragma unroll
    for (int mt = 0; mt < 2; mt++)
#pragma unroll
        for (int nt = 0; nt < 4; nt++)
#pragma unroll
            for (int i = 0; i < 4; i++) acc[mt][nt][i] = 0.f;

    for (int cn = 0; cn < NN / 64; cn++) {
        __syncthreads();   // prior OV mma done with sV/sP; K/Linv staged (1st)

        // store Q hi/lo
        {
            uint32_t h[4], l[4];
            hilo_pack8(qpre0, qpre1, h, l);
            STS128U(qb + SWZ((uint32_t)(qr * 128 + (tid & 3) * 16)),
                    h[0], h[1], h[2], h[3]);
            STS128U(qb + SWZ((uint32_t)(qr * 128 + 64 + (tid & 3) * 16)),
                    l[0], l[1], l[2], l[3]);
        }
        // store V bf16
#pragma unroll
        for (int jj = 0; jj < 4; jj++) {
            const float4 f0 = vpre[jj * 2];
            const float4 f1 = vpre[jj * 2 + 1];
            STS128U(vb + SWZ((uint32_t)(vrow * 128 + vqo * 2 + jj * 16)),
                    pack_bf16(f0.x, f0.y), pack_bf16(f0.z, f0.w),
                    pack_bf16(f1.x, f1.y), pack_bf16(f1.z, f1.w));
        }
        __syncthreads();

        // prefetch next chunk while mma runs
        if (cn + 1 < NN / 64) {
            const int qc = (cn + 1) * 64;
            const size_t qbase = (size_t)(qc + qr) * CQK + qf8;
            qpre0 = *(const float4*)&Qg[qbase];
            qpre1 = *(const float4*)&Qg[qbase + 4];
#pragma unroll
            for (int j = 0; j < 8; j++)
                vpre[j] = *(const float4*)&Vg[(size_t)vrow * NN + qc + vqo + j * 4];
        }

        // ---- S tile: 64k x 64q (warp = k16 x q32) ----
        float sa[4][4];
#pragma unroll
        for (int i = 0; i < 4; i++)
#pragma unroll
            for (int j = 0; j < 4; j++) sa[i][j] = 0.f;

#pragma unroll
        for (int s = 0; s < 2; s++) {
            uint32_t Ah[4], Al[4];
            LDMX4(Ah[0], Ah[1], Ah[2], Ah[3],
                  kb + SWZ((uint32_t)((swm * 16 + frow) * 128 + s * 32 + fhc)));
            LDMX4(Al[0], Al[1], Al[2], Al[3],
                  kb + SWZ((uint32_t)((swm * 16 + frow) * 128 + 64 + s * 32 + fhc)));
#pragma unroll
            for (int qg = 0; qg < 2; qg++) {
                uint32_t Bh[4], Bl[4];
                LDMX4(Bh[0], Bh[1], Bh[2], Bh[3],
                      qb + SWZ((uint32_t)((swq * 32 + qg * 16 + frow) * 128 + s * 32 + fhc)));
                LDMX4(Bl[0], Bl[1], Bl[2], Bl[3],
                      qb + SWZ((uint32_t)((swq * 32 + qg * 16 + frow) * 128 + 64 + s * 32 + fhc)));
                MMA16816(sa[qg*2+0], Ah[0], Ah[1], Ah[2], Ah[3], Bh[0], Bh[2]);
                MMA16816(sa[qg*2+1], Ah[0], Ah[1], Ah[2], Ah[3], Bh[1], Bh[3]);
                MMA16816(sa[qg*2+0], Ah[0], Ah[1], Ah[2], Ah[3], Bl[0], Bl[2]);
                MMA16816(sa[qg*2+1], Ah[0], Ah[1], Ah[2], Ah[3], Bl[1], Bl[3]);
                MMA16816(sa[qg*2+0], Al[0], Al[1], Al[2], Al[3], Bh[0], Bh[2]);
                MMA16816(sa[qg*2+1], Al[0], Al[1], Al[2], Al[3], Bh[1], Bh[3]);
            }
        }

        // P = exp(S) -> bf16 smem [k][q]
#pragma unroll
        for (int n8 = 0; n8 < 4; n8++) {
#pragma unroll
            for (int h2 = 0; h2 < 2; h2++) {
                const int kk = swm * 16 + er + h2 * 8;
                const int qq = swq * 32 + n8 * 8 + ec;
                const uint32_t pk = pack_bf16(__expf(sa[n8][h2 * 2]),
                                              __expf(sa[n8][h2 * 2 + 1]));
                STS32U(pb + SWZ((uint32_t)(kk * 128 + qq * 2)), pk);
            }
        }
        __syncthreads();

        // ---- OV mma: c 128 x k 64 (warp = c32 x k32) ----
#pragma unroll
        for (int qs = 0; qs < 4; qs++) {
            const int cb = qs * 32 + fhc;
            uint32_t A0[4], A1[4], B0[4], B1[4];
            LDMX4(A0[0], A0[1], A0[2], A0[3],
                  vb + SWZ((uint32_t)((wm * 32 + frow) * 128 + cb)));
            LDMX4(A1[0], A1[1], A1[2], A1[3],
                  vb + SWZ((uint32_t)((wm * 32 + 16 + frow) * 128 + cb)));
            LDMX4(B0[0], B0[1], B0[2], B0[3],
                  pb + SWZ((uint32_t)((wn * 32 + frow) * 128 + cb)));
            LDMX4(B1[0], B1[1], B1[2], B1[3],
                  pb + SWZ((uint32_t)((wn * 32 + 16 + frow) * 128 + cb)));

            MMA16816(acc[0][0], A0[0], A0[1], A0[2], A0[3], B0[0], B0[2]);
            MMA16816(acc[0][1], A0[0], A0[1], A0[2], A0[3], B0[1], B0[3]);
            MMA16816(acc[0][2], A0[0], A0[1], A0[2], A0[3], B1[0], B1[2]);
            MMA16816(acc[0][3], A0[0], A0[1], A0[2], A0[3], B1[1], B1[3]);
            MMA16816(acc[1][0], A1[0], A1[1], A1[2], A1[3], B0[0], B0[2]);
            MMA16816(acc[1][1], A1[0], A1[1], A1[2], A1[3], B0[1], B0[3]);
            MMA16816(acc[1][2], A1[0], A1[1], A1[2], A1[3], B1[0], B1[2]);
            MMA16816(acc[1][3], A1[0], A1[1], A1[2], A1[3], B1[1], B1[3]);
        }
    }

    // epilogue: out = x + g * Linv[k] * D
    const float g = gamma[0];
#pragma unroll
    for (int mt = 0; mt < 2; mt++) {
#pragma unroll
        for (int nt = 0; nt < 4; nt++) {
            const int kk = wn * 32 + nt * 8 + ec;
            const float l0 = sLinv[kk], l1 = sLinv[kk + 1];
#pragma unroll
            for (int h = 0; h < 2; h++) {
                const int c = c0 + wm * 32 + mt * 16 + er + h * 8;
                const size_t idx = ((size_t)b * CC + c) * NN + k0 + kk;
                const float2 xv = *(const float2*)&x[idx];
                float2 o;
                o.x = xv.x + g * l0 * acc[mt][nt][h * 2 + 0];
                o.y = xv.y + g * l1 * acc[mt][nt][h * 2 + 1];
                *(float2*)&out[idx] = o;
            }
        }
    }
}

// ============================================================
extern "C" void kernel_launch(void* const* d_in, const int* in_sizes, int n_in,
                              void* d_out, int out_size)
{
    const float* x     = (const float*)d_in[0];
    const float* wq    = (const float*)d_in[1];
    const float* bq    = (const float*)d_in[2];
    const float* wk    = (const float*)d_in[3];
    const float* bk    = (const float*)d_in[4];
    const float* wv    = (const float*)d_in[5];
    const float* bv    = (const float*)d_in[6];
    const float* gamma = (const float*)d_in[7];
    float* out = (float*)d_out;

    float *Qp, *Kp, *Vp;
    cudaGetSymbolAddress((void**)&Qp, g_Q);
    cudaGetSymbolAddress((void**)&Kp, g_K);
    cudaGetSymbolAddress((void**)&Vp, g_V);

    dim3 cblk(32, 8);
    conv3x3_kernel<<<dim3(2, 4, BB * (CQK / CO_T)), cblk>>>(x, wq, bq, Qp, CQK, 1);
    conv3x3_kernel<<<dim3(2, 4, BB * (CQK / CO_T)), cblk>>>(x, wk, bk, Kp, CQK, 1);
    conv3x3_kernel<<<dim3(2, 4, BB * (CC  / CO_T)), cblk>>>(x, wv, bv, Vp, CC, 0);

    stats_kernel<<<dim3(NN / 128, BB), 256>>>();
    fused_ov_kernel<<<dim3(NN / 64, CC / 128, BB), 256>>>(x, gamma, out);
}

// round 7
// speedup vs baseline: 1.7718x; 1.7718x over previous
#include <cuda_runtime.h>
#include <cuda_bf16.h>
#include <stdint.h>
#include <math.h>

#define BB 4
#define CC 256
#define HH 64
#define WW 64
#define NN (HH*WW)      // 4096
#define CQK 32

// ---- scratch (static device globals; no allocation) ----
__device__ float g_Q[BB*CQK*NN];                    // 2 MB   [b][d][n]
__device__ float g_K[BB*CQK*NN];                    // 2 MB   [b][d][n]
__device__ __nv_bfloat16 g_Vbf[BB*CC*NN];           // 8 MB   [b][c][n]
__device__ __nv_bfloat16 g_P[(size_t)BB*NN*NN];     // 128 MB P=exp(S^T): [b][k][q]
__device__ float g_Linv[BB*NN];                     // 1/column-sum (per k)

// ============================================================
// helpers
// ============================================================
__device__ __forceinline__ uint32_t smem_u32(const void* p) {
    uint32_t a;
    asm("{ .reg .u64 t; cvta.to.shared.u64 t, %1; cvt.u32.u64 %0, t; }"
        : "=r"(a) : "l"(p));
    return a;
}
#define SWZ(x) ((x) ^ (((x) >> 3) & 0x70))
#define STS128U(addr, a, b, c, d) \
    asm volatile("st.shared.v4.b32 [%0], {%1, %2, %3, %4};" \
                 :: "r"(addr), "r"(a), "r"(b), "r"(c), "r"(d) : "memory")
#define LDMX4(r0, r1, r2, r3, a) \
    asm volatile("ldmatrix.sync.aligned.m8n8.x4.shared.b16 {%0,%1,%2,%3}, [%4];" \
                 : "=r"(r0), "=r"(r1), "=r"(r2), "=r"(r3) : "r"(a))
#define MMA16816(d, a0, a1, a2, a3, b0, b1) \
    asm volatile("mma.sync.aligned.m16n8k16.row.col.f32.bf16.bf16.f32 " \
                 "{%0,%1,%2,%3}, {%4,%5,%6,%7}, {%8,%9}, {%0,%1,%2,%3};" \
                 : "+f"((d)[0]), "+f"((d)[1]), "+f"((d)[2]), "+f"((d)[3]) \
                 : "r"(a0), "r"(a1), "r"(a2), "r"(a3), "r"(b0), "r"(b1))

__device__ __forceinline__ uint32_t pack_bf16(float a, float b) {
    __nv_bfloat162 h = __floats2bfloat162_rn(a, b);
    return *(uint32_t*)&h;
}

// fast exp via FMA poly (avoids MUFU bottleneck; |x| < ~80, rel err ~4e-5)
__device__ __forceinline__ float fexp(float x) {
    const float t = x * 1.4426950408889634f;
    const float n = rintf(t);
    const float r = t - n;
    float p = 0.009618130f;
    p = fmaf(p, r, 0.055504110f);
    p = fmaf(p, r, 0.240226507f);
    p = fmaf(p, r, 0.693147181f);
    p = fmaf(p, r, 1.0f);
    return __int_as_float(__float_as_int(p) + ((int)n << 23));
}

// ============================================================
// Conv 3x3 SAME: tile 32x16 spatial, block (32,8), 2 rows/thread
// obf=0: fp32 out [b][co][n] ; obf=1: bf16 out [b][co][n]
// ============================================================
#define CI_T 4
#define CO_T 8

__global__ void __launch_bounds__(256) conv3x3_kernel(
    const float* __restrict__ x, const float* __restrict__ w,
    const float* __restrict__ bias, void* __restrict__ outv, int CO, int obf)
{
    __shared__ float xs[CI_T][18][34];
    __shared__ float ws[CO_T][CI_T][9];

    const int tx = threadIdx.x;            // 0..31
    const int ty = threadIdx.y;            // 0..7
    const int tid = ty * 32 + tx;
    const int tile_x = blockIdx.x * 32;
    const int tile_y = blockIdx.y * 16;
    const int cogs = CO / CO_T;
    const int cog = blockIdx.z % cogs;
    const int b   = blockIdx.z / cogs;
    const int co0 = cog * CO_T;

    float acc[CO_T][2];
#pragma unroll
    for (int i = 0; i < CO_T; i++) { acc[i][0] = 0.f; acc[i][1] = 0.f; }

    const float* xb = x + (size_t)b * CC * HH * WW;

    for (int ci0 = 0; ci0 < CC; ci0 += CI_T) {
        for (int idx = tid; idx < CI_T * 18 * 34; idx += 256) {
            int ci = idx / (18 * 34);
            int rr = (idx / 34) % 18;
            int cc = idx % 34;
            int gy = tile_y + rr - 1;
            int gx = tile_x + cc - 1;
            float v = 0.f;
            if (gy >= 0 && gy < HH && gx >= 0 && gx < WW)
                v = xb[(size_t)(ci0 + ci) * HH * WW + gy * WW + gx];
            xs[ci][rr][cc] = v;
        }
        for (int idx = tid; idx < CO_T * CI_T * 9; idx += 256) {
            int co = idx / (CI_T * 9);
            int rem = idx % (CI_T * 9);
            int ci = rem / 9;
            int t = rem % 9;
            ws[co][ci][t] = w[((size_t)(co0 + co) * CC + (ci0 + ci)) * 9 + t];
        }
        __syncthreads();

        const int oy = ty * 2;
#pragma unroll
        for (int ci = 0; ci < CI_T; ci++) {
            float xv[4][3];
#pragma unroll
            for (int rr = 0; rr < 4; rr++)
#pragma unroll
                for (int c2 = 0; c2 < 3; c2++)
                    xv[rr][c2] = xs[ci][oy + rr][tx + c2];
#pragma unroll
            for (int co = 0; co < CO_T; co++) {
#pragma unroll
                for (int t = 0; t < 9; t++) {
                    const int dy = t / 3, dx = t % 3;
                    const float wv = ws[co][ci][t];
                    acc[co][0] = fmaf(xv[0 + dy][dx], wv, acc[co][0]);
                    acc[co][1] = fmaf(xv[1 + dy][dx], wv, acc[co][1]);
                }
            }
        }
        __syncthreads();
    }

    if (obf) {
        __nv_bfloat16* ob = (__nv_bfloat16*)outv;
#pragma unroll
        for (int co = 0; co < CO_T; co++) {
            const float bv = bias[co0 + co];
#pragma unroll
            for (int r = 0; r < 2; r++) {
                const int gy = tile_y + ty * 2 + r;
                const int gx = tile_x + tx;
                ob[((size_t)b * CO + co0 + co) * HH * WW + gy * WW + gx] =
                    __float2bfloat16(acc[co][r] + bv);
            }
        }
    } else {
        float* of = (float*)outv;
#pragma unroll
        for (int co = 0; co < CO_T; co++) {
            const float bv = bias[co0 + co];
#pragma unroll
            for (int r = 0; r < 2; r++) {
                const int gy = tile_y + ty * 2 + r;
                const int gx = tile_x + tx;
                of[((size_t)b * CO + co0 + co) * HH * WW + gy * WW + gx] =
                    acc[co][r] + bv;
            }
        }
    }
}

// ============================================================
// qk: P[b][k][q] = exp( sum_d Q[b][d][q] * K[b][d][k] )  (bf16 out)
// ============================================================
__global__ void __launch_bounds__(256) qk_kernel()
{
    __shared__ float Qs[CQK][68];
    __shared__ float Ks[CQK][68];
    const int tid = threadIdx.x;
    const int q0 = blockIdx.x * 64;
    const int k0 = blockIdx.y * 64;
    const int b = blockIdx.z;

    const float* Qg = g_Q + (size_t)b * CQK * NN;
    const float* Kg = g_K + (size_t)b * CQK * NN;

    for (int idx = tid; idx < CQK * 64; idx += 256) {
        const int d = idx >> 6;
        const int j = idx & 63;
        Qs[d][j] = Qg[d * NN + q0 + j];
        Ks[d][j] = Kg[d * NN + k0 + j];
    }
    __syncthreads();

    const int kt = tid & 15;
    const int qt = tid >> 4;
    float acc[4][4] = {};
#pragma unroll
    for (int d = 0; d < CQK; d++) {
        const float4 a = *(const float4*)&Qs[d][qt * 4];
        const float4 bb = *(const float4*)&Ks[d][kt * 4];
        const float av[4] = {a.x, a.y, a.z, a.w};
        const float bv[4] = {bb.x, bb.y, bb.z, bb.w};
#pragma unroll
        for (int i = 0; i < 4; i++)
#pragma unroll
            for (int j = 0; j < 4; j++)
                acc[i][j] = fmaf(av[i], bv[j], acc[i][j]);
    }

    // P = exp(S), store transposed [k][q] as bf16 (uint2 over 4 q)
    __nv_bfloat16* Pb = g_P + (size_t)b * NN * NN;
#pragma unroll
    for (int j = 0; j < 4; j++) {
        const int k = k0 + kt * 4 + j;
        uint2 o;
        o.x = pack_bf16(fexp(acc[0][j]), fexp(acc[1][j]));
        o.y = pack_bf16(fexp(acc[2][j]), fexp(acc[3][j]));
        *(uint2*)&Pb[(size_t)k * NN + q0 + qt * 4] = o;
    }
}

// ============================================================
// psum: Linv[k] = 1 / sum_q P[k][q]   (bf16 row sum, fp32 accum)
// ============================================================
__global__ void __launch_bounds__(256) psum_kernel()
{
    __shared__ float red[8];
    const int k = blockIdx.x;
    const int b = blockIdx.y;
    const int tid = threadIdx.x;
    const int wid = tid >> 5, lid = tid & 31;
    const __nv_bfloat16* row = g_P + (size_t)b * NN * NN + (size_t)k * NN;

    float s = 0.f;
#pragma unroll
    for (int p = 0; p < 2; p++) {
        const uint4 v = *(const uint4*)&row[tid * 16 + p * 8];
        const uint32_t a[4] = {v.x, v.y, v.z, v.w};
#pragma unroll
        for (int e = 0; e < 4; e++) {
            const float2 f = __bfloat1622float2(*(const __nv_bfloat162*)&a[e]);
            s += f.x + f.y;
        }
    }
#pragma unroll
    for (int o = 16; o > 0; o >>= 1)
        s += __shfl_xor_sync(0xFFFFFFFF, s, o);
    if (lid == 0) red[wid] = s;
    __syncthreads();
    if (tid == 0) {
        float t = 0.f;
#pragma unroll
        for (int i = 0; i < 8; i++) t += red[i];
        g_Linv[b * NN + k] = 1.f / t;
    }
}

// ============================================================
// OV via mma.sync (HMMA bf16):
//   D[c,k] = sum_q V[c,q] * P[k,q] ;  out = x + gamma * Linv[k] * D
// Block tile: 128 c x 64 k, q-chunks of 64. 8 warps = 4(m) x 2(n).
// A = V bf16 [128][64], B = P bf16 [64][64]; both pure copies.
// ============================================================
#define OV_QC 64

__global__ void __launch_bounds__(256) ov_mma_kernel(
    const float* __restrict__ x, const float* __restrict__ gamma,
    float* __restrict__ out)
{
    // A: 128 rows * 128B = 16KB ; B: 64 rows * 128B = 8KB
    __shared__ uint32_t smem_raw[(16384 + 8192 + 128) / 4];
    __shared__ float Lsh[64];

    const int tid = threadIdx.x;
    const int wid = tid >> 5;
    const int lid = tid & 31;
    const int wm = wid >> 1;            // 0..3 : c block of 32
    const int wn = wid & 1;             // 0..1 : k block of 32
    const int k0 = blockIdx.x * 64;
    const int c0 = blockIdx.y * 128;
    const int b  = blockIdx.z;

    const uint32_t abase = (smem_u32(smem_raw) + 127) & ~127u;
    const uint32_t bbase = abase + 16384;

    if (tid < 64) Lsh[tid] = g_Linv[b * NN + k0 + tid];

    const __nv_bfloat16* Vg = g_Vbf + ((size_t)b * CC + c0) * NN;
    const __nv_bfloat16* Pg = g_P + (size_t)b * NN * NN;

    const int jrow = tid >> 3;          // 0..31
    const int qoff = (tid & 7) * 8;     // 0..56 (elements)

    uint4 a_pre[4];
    uint4 b_pre[2];

    // prefetch chunk 0
#pragma unroll
    for (int j = 0; j < 4; j++)
        a_pre[j] = *(const uint4*)&Vg[(size_t)(jrow + j * 32) * NN + qoff];
#pragma unroll
    for (int p = 0; p < 2; p++)
        b_pre[p] = *(const uint4*)&Pg[(size_t)(k0 + jrow + p * 32) * NN + qoff];

    float acc[2][4][4];
#pragma unroll
    for (int mt = 0; mt < 2; mt++)
#pragma unroll
        for (int nt = 0; nt < 4; nt++)
#pragma unroll
            for (int i = 0; i < 4; i++) acc[mt][nt][i] = 0.f;

    for (int chunk = 0; chunk < NN / OV_QC; chunk++) {
        __syncthreads();   // previous mma reads done (also covers Lsh on c0)

        // store A tile (pure copy)
#pragma unroll
        for (int j = 0; j < 4; j++) {
            const int row = jrow + j * 32;
            STS128U(abase + SWZ((uint32_t)(row * 128 + qoff * 2)),
                    a_pre[j].x, a_pre[j].y, a_pre[j].z, a_pre[j].w);
        }
        // store B tile (pure copy)
#pragma unroll
        for (int p = 0; p < 2; p++) {
            const int row = jrow + p * 32;
            STS128U(bbase + SWZ((uint32_t)(row * 128 + qoff * 2)),
                    b_pre[p].x, b_pre[p].y, b_pre[p].z, b_pre[p].w);
        }
        __syncthreads();

        // prefetch next chunk (overlaps with mma below)
        if (chunk + 1 < NN / OV_QC) {
            const int qc = (chunk + 1) * OV_QC;
#pragma unroll
            for (int j = 0; j < 4; j++)
                a_pre[j] = *(const uint4*)&Vg[(size_t)(jrow + j * 32) * NN + qc + qoff];
#pragma unroll
            for (int p = 0; p < 2; p++)
                b_pre[p] = *(const uint4*)&Pg[(size_t)(k0 + jrow + p * 32) * NN + qc + qoff];
        }

        // mma over 4 k16 steps
        const int frow = lid & 15;
        const int fcb  = (lid >> 4) * 16;
#pragma unroll
        for (int qs = 0; qs < 4; qs++) {
            const int cb = qs * 32 + fcb;
            uint32_t A0[4], A1[4], B0[4], B1[4];
            LDMX4(A0[0], A0[1], A0[2], A0[3],
                  abase + SWZ((uint32_t)((wm * 32 + frow) * 128 + cb)));
            LDMX4(A1[0], A1[1], A1[2], A1[3],
                  abase + SWZ((uint32_t)((wm * 32 + 16 + frow) * 128 + cb)));
            LDMX4(B0[0], B0[1], B0[2], B0[3],
                  bbase + SWZ((uint32_t)((wn * 32 + frow) * 128 + cb)));
            LDMX4(B1[0], B1[1], B1[2], B1[3],
                  bbase + SWZ((uint32_t)((wn * 32 + 16 + frow) * 128 + cb)));

            MMA16816(acc[0][0], A0[0], A0[1], A0[2], A0[3], B0[0], B0[2]);
            MMA16816(acc[0][1], A0[0], A0[1], A0[2], A0[3], B0[1], B0[3]);
            MMA16816(acc[0][2], A0[0], A0[1], A0[2], A0[3], B1[0], B1[2]);
            MMA16816(acc[0][3], A0[0], A0[1], A0[2], A0[3], B1[1], B1[3]);
            MMA16816(acc[1][0], A1[0], A1[1], A1[2], A1[3], B0[0], B0[2]);
            MMA16816(acc[1][1], A1[0], A1[1], A1[2], A1[3], B0[1], B0[3]);
            MMA16816(acc[1][2], A1[0], A1[1], A1[2], A1[3], B1[0], B1[2]);
            MMA16816(acc[1][3], A1[0], A1[1], A1[2], A1[3], B1[1], B1[3]);
        }
    }

    // epilogue: out = x + g * Linv[k] * D
    const float g = gamma[0];
    const int er = lid >> 2;
    const int ec = (lid & 3) * 2;
#pragma unroll
    for (int mt = 0; mt < 2; mt++) {
#pragma unroll
        for (int nt = 0; nt < 4; nt++) {
            const int kk = wn * 32 + nt * 8 + ec;
            const float l0 = Lsh[kk], l1 = Lsh[kk + 1];
#pragma unroll
            for (int h = 0; h < 2; h++) {
                const int c = c0 + wm * 32 + mt * 16 + er + h * 8;
                const size_t idx = ((size_t)b * CC + c) * NN + k0 + kk;
                const float2 xv = *(const float2*)&x[idx];
                float2 o;
                o.x = xv.x + g * l0 * acc[mt][nt][h * 2 + 0];
                o.y = xv.y + g * l1 * acc[mt][nt][h * 2 + 1];
                *(float2*)&out[idx] = o;
            }
        }
    }
}

// ============================================================
extern "C" void kernel_launch(void* const* d_in, const int* in_sizes, int n_in,
                              void* d_out, int out_size)
{
    const float* x     = (const float*)d_in[0];
    const float* wq    = (const float*)d_in[1];
    const float* bq    = (const float*)d_in[2];
    const float* wk    = (const float*)d_in[3];
    const float* bk    = (const float*)d_in[4];
    const float* wv    = (const float*)d_in[5];
    const float* bv    = (const float*)d_in[6];
    const float* gamma = (const float*)d_in[7];
    float* out = (float*)d_out;

    float *Qp, *Kp;
    __nv_bfloat16* Vbp;
    cudaGetSymbolAddress((void**)&Qp, g_Q);
    cudaGetSymbolAddress((void**)&Kp, g_K);
    cudaGetSymbolAddress((void**)&Vbp, g_Vbf);

    dim3 cblk(32, 8);
    conv3x3_kernel<<<dim3(2, 4, BB * (CQK / CO_T)), cblk>>>(x, wq, bq, Qp, CQK, 0);
    conv3x3_kernel<<<dim3(2, 4, BB * (CQK / CO_T)), cblk>>>(x, wk, bk, Kp, CQK, 0);
    conv3x3_kernel<<<dim3(2, 4, BB * (CC  / CO_T)), cblk>>>(x, wv, bv, Vbp, CC, 1);

    qk_kernel<<<dim3(NN / 64, NN / 64, BB), 256>>>();
    psum_kernel<<<dim3(NN, BB), 256>>>();
    ov_mma_kernel<<<dim3(NN / 64, CC / 128, BB), 256>>>(x, gamma, out);
}

// round 10
// speedup vs baseline: 5.7665x; 3.2546x over previous
#include <cuda_runtime.h>
#include <cuda_bf16.h>
#include <stdint.h>
#include <math.h>

#define BB 4
#define CC 256
#define HH 64
#define WW 64
#define NN (HH*WW)      // 4096
#define CQK 32

// ---- scratch (static device globals; no allocation) ----
__device__ float g_Q[BB*CQK*NN];                    // 2 MB   [b][d][n]
__device__ float g_K[BB*CQK*NN];                    // 2 MB   [b][d][n]
__device__ __nv_bfloat16 g_Vbf[BB*CC*NN];           // 8 MB   [b][c][n]
__device__ __nv_bfloat16 g_P[(size_t)BB*NN*NN];     // 128 MB P=exp(S^T): [b][k][q]
__device__ float g_Linv[BB*NN];                     // 1/column-sum (per k)
__device__ __nv_bfloat16 g_xT[(size_t)BB*NN*CC];    // 8 MB   xT: [b][n][ci]
__device__ __nv_bfloat16 g_WtV[9*CC*CC];            // 1.1 MB [t][co][ci]
__device__ __nv_bfloat16 g_WtQK[9*64*CC];           // 288 KB [t][co(q0-31,k32-63)][ci]

// ============================================================
// helpers
// ============================================================
__device__ __forceinline__ uint32_t smem_u32(const void* p) {
    uint32_t a;
    asm("{ .reg .u64 t; cvta.to.shared.u64 t, %1; cvt.u32.u64 %0, t; }"
        : "=r"(a) : "l"(p));
    return a;
}
#define SWZ(x) ((x) ^ (((x) >> 3) & 0x70))
#define STS128U(addr, a, b, c, d) \
    asm volatile("st.shared.v4.b32 [%0], {%1, %2, %3, %4};" \
                 :: "r"(addr), "r"(a), "r"(b), "r"(c), "r"(d) : "memory")
#define STS32U(addr, a) \
    asm volatile("st.shared.b32 [%0], %1;" :: "r"(addr), "r"(a) : "memory")
#define LDMX4(r0, r1, r2, r3, a) \
    asm volatile("ldmatrix.sync.aligned.m8n8.x4.shared.b16 {%0,%1,%2,%3}, [%4];" \
                 : "=r"(r0), "=r"(r1), "=r"(r2), "=r"(r3) : "r"(a))
#define MMA16816(d, a0, a1, a2, a3, b0, b1) \
    asm volatile("mma.sync.aligned.m16n8k16.row.col.f32.bf16.bf16.f32 " \
                 "{%0,%1,%2,%3}, {%4,%5,%6,%7}, {%8,%9}, {%0,%1,%2,%3};" \
                 : "+f"((d)[0]), "+f"((d)[1]), "+f"((d)[2]), "+f"((d)[3]) \
                 : "r"(a0), "r"(a1), "r"(a2), "r"(a3), "r"(b0), "r"(b1))

__device__ __forceinline__ uint32_t pack_bf16(float a, float b) {
    __nv_bfloat162 h = __floats2bfloat162_rn(a, b);
    return *(uint32_t*)&h;
}

// fast exp via FMA poly (avoids MUFU bottleneck; |x| < ~80, rel err ~4e-5)
__device__ __forceinline__ float fexp(float x) {
    const float t = x * 1.4426950408889634f;
    const float n = rintf(t);
    const float r = t - n;
    float p = 0.009618130f;
    p = fmaf(p, r, 0.055504110f);
    p = fmaf(p, r, 0.240226507f);
    p = fmaf(p, r, 0.693147181f);
    p = fmaf(p, r, 1.0f);
    return __int_as_float(__float_as_int(p) + ((int)n << 23));
}

// ============================================================
// transpose: xT[b][n][ci] (bf16) from x[b][ci][n] (fp32)
// ============================================================
__global__ void __launch_bounds__(256) transpose_kernel(
    const float* __restrict__ x, __nv_bfloat16* __restrict__ xT)
{
    __shared__ float t[32][33];
    const int tx = threadIdx.x, ty = threadIdx.y;
    const int n0 = blockIdx.x * 32, ci0 = blockIdx.y * 32, b = blockIdx.z;
#pragma unroll
    for (int j = 0; j < 4; j++)
        t[ty + j * 8][tx] = x[((size_t)b * CC + ci0 + ty + j * 8) * NN + n0 + tx];
    __syncthreads();
#pragma unroll
    for (int j = 0; j < 4; j++) {
        const int n = n0 + ty + j * 8;
        xT[((size_t)b * NN + n) * CC + ci0 + tx] = __float2bfloat16(t[tx][ty + j * 8]);
    }
}

// ============================================================
// weight packing: Wt[t][co][ci] bf16 from w[co][ci][t] fp32
// ============================================================
__global__ void pack_wv_kernel(const float* __restrict__ wv,
                               __nv_bfloat16* __restrict__ Wt)
{
    const int i = blockIdx.x * 256 + threadIdx.x;   // 9*256*256
    const int t = i / (CC * CC);
    const int r = i % (CC * CC);
    const int co = r >> 8, ci = r & 255;
    Wt[i] = __float2bfloat16(wv[((size_t)co * CC + ci) * 9 + t]);
}
__global__ void pack_wqk_kernel(const float* __restrict__ wq,
                                const float* __restrict__ wk,
                                __nv_bfloat16* __restrict__ Wt)
{
    const int i = blockIdx.x * 256 + threadIdx.x;   // 9*64*256
    const int t = i / (64 * CC);
    const int r = i % (64 * CC);
    const int co = r >> 8, ci = r & 255;
    const float v = (co < 32) ? wq[((size_t)co * CC + ci) * 9 + t]
                              : wk[((size_t)(co - 32) * CC + ci) * 9 + t];
    Wt[i] = __float2bfloat16(v);
}

// ============================================================
// implicit-GEMM conv3x3 via mma.sync
//   out[co][n] = bias[co] + sum_t sum_ci Wt[t][co][ci] * xT[n+off_t][ci]
// Block: n-tile 128 (2 image rows), co-tile COT. ci-chunks of 64,
// x-strip (4 rows + zero row) staged per chunk, reused by all 9 taps.
// Boundary pixels redirect to the zero row via per-lane ldmatrix addrs.
// MODE 0: bf16 out [b][256][n] (V).  MODE 1: fp32 split q/k [b][32][n].
// ============================================================
template<int COT, int MODE>
__global__ void __launch_bounds__(256) conv_mma_kernel(
    const __nv_bfloat16* __restrict__ xT,
    const __nv_bfloat16* __restrict__ Wt,
    const float* __restrict__ bias0, const float* __restrict__ bias1,
    void* __restrict__ out0, void* __restrict__ out1)
{
    extern __shared__ uint8_t dynsmem[];
    constexpr int COTOT = (MODE == 0) ? 256 : 64;   // Wt rows per tap
    constexpr int MW = COT / 32;     // m warps
    constexpr int NW = 8 / MW;       // n warps
    constexpr int NT = 128 / NW;     // warp n-tile (px)
    constexpr int NB8 = NT / 8;
    constexpr int NBG = NT / 16;

    const int tid = threadIdx.x;
    const int wid = tid >> 5, lid = tid & 31;
    const int wm = wid / NW, wn = wid % NW;
    const int y0 = blockIdx.x * 2;
    const int n0 = y0 * 64;
    const int co0 = blockIdx.y * COT;
    const int b = blockIdx.z;

    const uint32_t sbase = (smem_u32(dynsmem) + 1023) & ~1023u;
    const uint32_t abase = sbase + 33792;

    // zero row at strip slot 256
    if (tid < 32) STS32U(sbase + 32768 + tid * 4, 0u);

    const int frow = lid & 15;
    const int fcb = (lid >> 4) * 16;

    float acc[2][NB8][4];
#pragma unroll
    for (int mt = 0; mt < 2; mt++)
#pragma unroll
        for (int nb = 0; nb < NB8; nb++)
#pragma unroll
            for (int i = 0; i < 4; i++) acc[mt][nb][i] = 0.f;

    // strip staging geometry: thread = one pixel slot (4 rows x 64 px)
    const int spx = tid & 63, sry = tid >> 6;
    const int sy = y0 - 1 + sry;
    const bool srow_ok = (sy >= 0) && (sy < HH);
    const uint8_t* xrow = (const uint8_t*)(xT +
        ((size_t)b * NN + (srow_ok ? sy : 0) * 64 + spx) * CC);

    for (int ci0 = 0; ci0 < CC; ci0 += 64) {
        __syncthreads();   // prior tap's mma done before strip overwrite
        // stage strip: 256 px x 64 ci (128B rows)
#pragma unroll
        for (int j = 0; j < 8; j++) {
            uint4 d = make_uint4(0, 0, 0, 0);
            if (srow_ok) d = *(const uint4*)(xrow + ci0 * 2 + j * 16);
            STS128U(sbase + SWZ((uint32_t)(tid * 128 + j * 16)), d.x, d.y, d.z, d.w);
        }
        for (int tap = 0; tap < 9; tap++) {
            __syncthreads();   // strip ready / prior mma done before A overwrite
            // stage A: COT rows x 64 ci
#pragma unroll
            for (int j = 0; j < COT / 32; j++) {
                const int i = j * 256 + tid;         // uint4 index
                const int row = i >> 3;
                const int cb = (i & 7) * 16;
                const uint8_t* src = (const uint8_t*)Wt +
                    (((size_t)tap * COTOT + co0 + row) * CC + ci0) * 2 + cb;
                const uint4 d = *(const uint4*)src;
                STS128U(abase + SWZ((uint32_t)(row * 128 + cb)), d.x, d.y, d.z, d.w);
            }
            __syncthreads();   // A ready

            // per-lane B row bases for this tap (boundary -> zero row)
            const int dy = tap / 3 - 1, dx = tap % 3 - 1;
            uint32_t brow[NBG];
#pragma unroll
            for (int g = 0; g < NBG; g++) {
                const int pn = wn * NT + g * 16 + frow;
                const int py = pn >> 6, px = pn & 63;
                const int yy = y0 + py + dy;
                const int xx = px + dx;
                const bool ok = (yy >= 0) && (yy < HH) && (xx >= 0) && (xx < WW);
                brow[g] = ok ? (uint32_t)(((py + dy + 1) * 64 + xx) * 128) : 32768u;
            }

#pragma unroll
            for (int ks = 0; ks < 4; ks++) {
                const uint32_t cib = ks * 32 + fcb;
                uint32_t Am[2][4];
#pragma unroll
                for (int mt = 0; mt < 2; mt++)
                    LDMX4(Am[mt][0], Am[mt][1], Am[mt][2], Am[mt][3],
                          abase + SWZ((uint32_t)((wm * 32 + mt * 16 + frow) * 128) + 0u * cib
                                      + ((uint32_t)((wm * 32 + mt * 16 + frow) * 128 + cib)
                                         - (uint32_t)((wm * 32 + mt * 16 + frow) * 128))));
                // NOTE: the expression above must be SWZ(rowbyte + cib); rewrite clean:
                (void)0;
#pragma unroll
                for (int mt = 0; mt < 2; mt++)
                    LDMX4(Am[mt][0], Am[mt][1], Am[mt][2], Am[mt][3],
                          abase + SWZ((uint32_t)((wm * 32 + mt * 16 + frow) * 128 + cib)));
                uint32_t Bf[NBG][4];
#pragma unroll
                for (int g = 0; g < NBG; g++)
                    LDMX4(Bf[g][0], Bf[g][1], Bf[g][2], Bf[g][3],
                          sbase + SWZ(brow[g] + cib));
#pragma unroll
                for (int mt = 0; mt < 2; mt++)
#pragma unroll
                    for (int g = 0; g < NBG; g++) {
                        MMA16816(acc[mt][2 * g],     Am[mt][0], Am[mt][1], Am[mt][2], Am[mt][3],
                                 Bf[g][0], Bf[g][2]);
                        MMA16816(acc[mt][2 * g + 1], Am[mt][0], Am[mt][1], Am[mt][2], Am[mt][3],
                                 Bf[g][1], Bf[g][3]);
                    }
            }
        }
    }

    // epilogue
    const int er = lid >> 2, ec = (lid & 3) * 2;
    if (MODE == 0) {
        __nv_bfloat16* ov = (__nv_bfloat16*)out0;
#pragma unroll
        for (int mt = 0; mt < 2; mt++)
#pragma unroll
            for (int h = 0; h < 2; h++) {
                const int co = wm * 32 + mt * 16 + er + h * 8;
                const float bb = bias0[co0 + co];
#pragma unroll
                for (int nb = 0; nb < NB8; nb++) {
                    const int n = n0 + wn * NT + nb * 8 + ec;
                    const uint32_t pk = pack_bf16(acc[mt][nb][h * 2] + bb,
                                                  acc[mt][nb][h * 2 + 1] + bb);
                    *(uint32_t*)&ov[((size_t)b * CC + co0 + co) * NN + n] = pk;
                }
            }
    } else {
#pragma unroll
        for (int mt = 0; mt < 2; mt++)
#pragma unroll
            for (int h = 0; h < 2; h++) {
                const int co = wm * 32 + mt * 16 + er + h * 8;
                float* dst; int d; float bb;
                if (co < 32) { dst = (float*)out0; d = co;      bb = bias0[d]; }
                else         { dst = (float*)out1; d = co - 32; bb = bias1[d]; }
#pragma unroll
                for (int nb = 0; nb < NB8; nb++) {
                    const int n = n0 + wn * NT + nb * 8 + ec;
                    float2 o;
                    o.x = acc[mt][nb][h * 2] + bb;
                    o.y = acc[mt][nb][h * 2 + 1] + bb;
                    *(float2*)&dst[((size_t)b * CQK + d) * NN + n] = o;
                }
            }
    }
}

// ============================================================
// qk: P[b][k][q] = exp( sum_d Q[b][d][q] * K[b][d][k] )  (bf16 out)
// ============================================================
__global__ void __launch_bounds__(256) qk_kernel()
{
    __shared__ float Qs[CQK][68];
    __shared__ float Ks[CQK][68];
    const int tid = threadIdx.x;
    const int q0 = blockIdx.x * 64;
    const int k0 = blockIdx.y * 64;
    const int b = blockIdx.z;

    const float* Qg = g_Q + (size_t)b * CQK * NN;
    const float* Kg = g_K + (size_t)b * CQK * NN;

    for (int idx = tid; idx < CQK * 64; idx += 256) {
        const int d = idx >> 6;
        const int j = idx & 63;
        Qs[d][j] = Qg[d * NN + q0 + j];
        Ks[d][j] = Kg[d * NN + k0 + j];
    }
    __syncthreads();

    const int kt = tid & 15;
    const int qt = tid >> 4;
    float acc[4][4] = {};
#pragma unroll
    for (int d = 0; d < CQK; d++) {
        const float4 a = *(const float4*)&Qs[d][qt * 4];
        const float4 bb = *(const float4*)&Ks[d][kt * 4];
        const float av[4] = {a.x, a.y, a.z, a.w};
        const float bv[4] = {bb.x, bb.y, bb.z, bb.w};
#pragma unroll
        for (int i = 0; i < 4; i++)
#pragma unroll
            for (int j = 0; j < 4; j++)
                acc[i][j] = fmaf(av[i], bv[j], acc[i][j]);
    }

    __nv_bfloat16* Pb = g_P + (size_t)b * NN * NN;
#pragma unroll
    for (int j = 0; j < 4; j++) {
        const int k = k0 + kt * 4 + j;
        uint2 o;
        o.x = pack_bf16(fexp(acc[0][j]), fexp(acc[1][j]));
        o.y = pack_bf16(fexp(acc[2][j]), fexp(acc[3][j]));
        *(uint2*)&Pb[(size_t)k * NN + q0 + qt * 4] = o;
    }
}

// ============================================================
// psum: Linv[k] = 1 / sum_q P[k][q]
// ============================================================
__global__ void __launch_bounds__(256) psum_kernel()
{
    __shared__ float red[8];
    const int k = blockIdx.x;
    const int b = blockIdx.y;
    const int tid = threadIdx.x;
    const int wid = tid >> 5, lid = tid & 31;
    const __nv_bfloat16* row = g_P + (size_t)b * NN * NN + (size_t)k * NN;

    float s = 0.f;
#pragma unroll
    for (int p = 0; p < 2; p++) {
        const uint4 v = *(const uint4*)&row[tid * 16 + p * 8];
        const uint32_t a[4] = {v.x, v.y, v.z, v.w};
#pragma unroll
        for (int e = 0; e < 4; e++) {
            const float2 f = __bfloat1622float2(*(const __nv_bfloat162*)&a[e]);
            s += f.x + f.y;
        }
    }
#pragma unroll
    for (int o = 16; o > 0; o >>= 1)
        s += __shfl_xor_sync(0xFFFFFFFF, s, o);
    if (lid == 0) red[wid] = s;
    __syncthreads();
    if (tid == 0) {
        float t = 0.f;
#pragma unroll
        for (int i = 0; i < 8; i++) t += red[i];
        g_Linv[b * NN + k] = 1.f / t;
    }
}

// ============================================================
// OV via mma.sync: D[c,k] = sum_q V[c,q]*P[k,q]
// Block tile: 128 c x 128 k, q-chunks 64. 8 warps = 4(m) x 2(n),
// warp = 32c x 64k. out = x + gamma * Linv[k] * D
// ============================================================
__global__ void __launch_bounds__(256) ov_mma_kernel(
    const float* __restrict__ x, const float* __restrict__ gamma,
    float* __restrict__ out)
{
    __shared__ uint32_t smem_raw[(16384 + 16384 + 128) / 4];
    __shared__ float Lsh[128];

    const int tid = threadIdx.x;
    const int wid = tid >> 5;
    const int lid = tid & 31;
    const int wm = wid >> 1;            // 0..3 : c block of 32
    const int wn = wid & 1;             // 0..1 : k block of 64
    const int k0 = blockIdx.x * 128;
    const int c0 = blockIdx.y * 128;
    const int b  = blockIdx.z;

    const uint32_t abase = (smem_u32(smem_raw) + 127) & ~127u;
    const uint32_t bbase = abase + 16384;

    if (tid < 128) Lsh[tid] = g_Linv[b * NN + k0 + tid];

    const __nv_bfloat16* Vg = g_Vbf + ((size_t)b * CC + c0) * NN;
    const __nv_bfloat16* Pg = g_P + (size_t)b * NN * NN;

    const int srow = tid >> 1;          // 0..127
    const int qo = (tid & 1) * 32;      // element offset (half row)

    uint4 a_pre[4], b_pre[4];
#pragma unroll
    for (int j = 0; j < 4; j++) {
        a_pre[j] = *(const uint4*)&Vg[(size_t)srow * NN + qo + j * 8];
        b_pre[j] = *(const uint4*)&Pg[(size_t)(k0 + srow) * NN + qo + j * 8];
    }

    float acc[2][8][4];
#pragma unroll
    for (int mt = 0; mt < 2; mt++)
#pragma unroll
        for (int nt = 0; nt < 8; nt++)
#pragma unroll
            for (int i = 0; i < 4; i++) acc[mt][nt][i] = 0.f;

    const int frow = lid & 15;
    const int fcb  = (lid >> 4) * 16;

    for (int chunk = 0; chunk < NN / 64; chunk++) {
        __syncthreads();
#pragma unroll
        for (int j = 0; j < 4; j++) {
            STS128U(abase + SWZ((uint32_t)(srow * 128 + qo * 2 + j * 16)),
                    a_pre[j].x, a_pre[j].y, a_pre[j].z, a_pre[j].w);
            STS128U(bbase + SWZ((uint32_t)(srow * 128 + qo * 2 + j * 16)),
                    b_pre[j].x, b_pre[j].y, b_pre[j].z, b_pre[j].w);
        }
        __syncthreads();

        if (chunk + 1 < NN / 64) {
            const int qc = (chunk + 1) * 64;
#pragma unroll
            for (int j = 0; j < 4; j++) {
                a_pre[j] = *(const uint4*)&Vg[(size_t)srow * NN + qc + qo + j * 8];
                b_pre[j] = *(const uint4*)&Pg[(size_t)(k0 + srow) * NN + qc + qo + j * 8];
            }
        }

#pragma unroll
        for (int ks = 0; ks < 4; ks++) {
            const uint32_t cib = ks * 32 + fcb;
            uint32_t Am[2][4];
#pragma unroll
            for (int mt = 0; mt < 2; mt++)
                LDMX4(Am[mt][0], Am[mt][1], Am[mt][2], Am[mt][3],
                      abase + SWZ((uint32_t)((wm * 32 + mt * 16 + frow) * 128 + cib)));
            uint32_t Bf[4][4];
#pragma unroll
            for (int g = 0; g < 4; g++)
                LDMX4(Bf[g][0], Bf[g][1], Bf[g][2], Bf[g][3],
                      bbase + SWZ((uint32_t)((wn * 64 + g * 16 + frow) * 128 + cib)));
#pragma unroll
            for (int mt = 0; mt < 2; mt++)
#pragma unroll
                for (int g = 0; g < 4; g++) {
                    MMA16816(acc[mt][2 * g],     Am[mt][0], Am[mt][1], Am[mt][2], Am[mt][3],
                             Bf[g][0], Bf[g][2]);
                    MMA16816(acc[mt][2 * g + 1], Am[mt][0], Am[mt][1], Am[mt][2], Am[mt][3],
                             Bf[g][1], Bf[g][3]);
                }
        }
    }

    // epilogue: out = x + g * Linv[k] * D
    const float g = gamma[0];
    const int er = lid >> 2;
    const int ec = (lid & 3) * 2;
#pragma unroll
    for (int mt = 0; mt < 2; mt++) {
#pragma unroll
        for (int nt = 0; nt < 8; nt++) {
            const int kk = wn * 64 + nt * 8 + ec;
            const float l0 = Lsh[kk], l1 = Lsh[kk + 1];
#pragma unroll
            for (int h = 0; h < 2; h++) {
                const int c = c0 + wm * 32 + mt * 16 + er + h * 8;
                const size_t idx = ((size_t)b * CC + c) * NN + k0 + kk;
                const float2 xv = *(const float2*)&x[idx];
                float2 o;
                o.x = xv.x + g * l0 * acc[mt][nt][h * 2 + 0];
                o.y = xv.y + g * l1 * acc[mt][nt][h * 2 + 1];
                *(float2*)&out[idx] = o;
            }
        }
    }
}

// ============================================================
extern "C" void kernel_launch(void* const* d_in, const int* in_sizes, int n_in,
                              void* d_out, int out_size)
{
    const float* x     = (const float*)d_in[0];
    const float* wq    = (const float*)d_in[1];
    const float* bq    = (const float*)d_in[2];
    const float* wk    = (const float*)d_in[3];
    const float* bk    = (const float*)d_in[4];
    const float* wv    = (const float*)d_in[5];
    const float* bv    = (const float*)d_in[6];
    const float* gamma = (const float*)d_in[7];
    float* out = (float*)d_out;

    float *Qp, *Kp;
    __nv_bfloat16 *Vbp, *xTp, *WtVp, *WtQKp;
    cudaGetSymbolAddress((void**)&Qp, g_Q);
    cudaGetSymbolAddress((void**)&Kp, g_K);
    cudaGetSymbolAddress((void**)&Vbp, g_Vbf);
    cudaGetSymbolAddress((void**)&xTp, g_xT);
    cudaGetSymbolAddress((void**)&WtVp, g_WtV);
    cudaGetSymbolAddress((void**)&WtQKp, g_WtQK);

    static int attr_set = 0;
    const int SMV = 1024 + 33792 + 16384;   // 51200
    const int SMQK = 1024 + 33792 + 8192;   // 43008
    if (!attr_set) {
        cudaFuncSetAttribute(conv_mma_kernel<128, 0>,
                             cudaFuncAttributeMaxDynamicSharedMemorySize, SMV);
        cudaFuncSetAttribute(conv_mma_kernel<64, 1>,
                             cudaFuncAttributeMaxDynamicSharedMemorySize, SMQK);
        attr_set = 1;
    }

    transpose_kernel<<<dim3(NN / 32, CC / 32, BB), dim3(32, 8)>>>(x, xTp);
    pack_wv_kernel<<<(9 * CC * CC) / 256, 256>>>(wv, WtVp);
    pack_wqk_kernel<<<(9 * 64 * CC) / 256, 256>>>(wq, wk, WtQKp);

    conv_mma_kernel<128, 0><<<dim3(32, 2, BB), 256, SMV>>>(
        xTp, WtVp, bv, nullptr, Vbp, nullptr);
    conv_mma_kernel<64, 1><<<dim3(32, 1, BB), 256, SMQK>>>(
        xTp, WtQKp, bq, bk, Qp, Kp);

    qk_kernel<<<dim3(NN / 64, NN / 64, BB), 256>>>();
    psum_kernel<<<dim3(NN, BB), 256>>>();
    ov_mma_kernel<<<dim3(NN / 128, CC / 128, BB), 256>>>(x, gamma, out);
}

// round 11
// speedup vs baseline: 7.1788x; 1.2449x over previous
#include <cuda_runtime.h>
#include <cuda_bf16.h>
#include <stdint.h>
#include <math.h>

#define BB 4
#define CC 256
#define HH 64
#define WW 64
#define NN (HH*WW)      // 4096
#define CQK 32

// ---- scratch (static device globals; no allocation) ----
__device__ float g_Q[BB*CQK*NN];                    // 2 MB   [b][d][n] (conv out)
__device__ float g_K[BB*CQK*NN];                    // 2 MB   [b][d][n] (conv out)
__device__ __nv_bfloat16 g_Qhl[BB*NN*64];           // 2 MB   [b][n][hi d0..31 | lo d0..31]
__device__ __nv_bfloat16 g_Khl[BB*NN*64];           // 2 MB   [b][n][hi | lo]
__device__ __nv_bfloat16 g_Vbf[BB*CC*NN];           // 8 MB   [b][c][n]
__device__ __nv_bfloat16 g_P[(size_t)BB*NN*NN];     // 128 MB P=exp(S^T): [b][k][q]
__device__ float g_Lpart[BB*NN*2];                  // partial col sums (per k, q-half)
__device__ __nv_bfloat16 g_xT[(size_t)BB*NN*CC];    // 8 MB   xT: [b][n][ci]
__device__ __nv_bfloat16 g_WtV[9*CC*CC];            // 1.1 MB [t][co][ci]
__device__ __nv_bfloat16 g_WtQK[9*64*CC];           // 288 KB [t][co(q0-31,k32-63)][ci]

// ============================================================
// helpers
// ============================================================
__device__ __forceinline__ uint32_t smem_u32(const void* p) {
    uint32_t a;
    asm("{ .reg .u64 t; cvta.to.shared.u64 t, %1; cvt.u32.u64 %0, t; }"
        : "=r"(a) : "l"(p));
    return a;
}
#define SWZ(x) ((x) ^ (((x) >> 3) & 0x70))
#define STS128U(addr, a, b, c, d) \
    asm volatile("st.shared.v4.b32 [%0], {%1, %2, %3, %4};" \
                 :: "r"(addr), "r"(a), "r"(b), "r"(c), "r"(d) : "memory")
#define STS32U(addr, a) \
    asm volatile("st.shared.b32 [%0], %1;" :: "r"(addr), "r"(a) : "memory")
#define LDS128U(r0, r1, r2, r3, addr) \
    asm volatile("ld.shared.v4.b32 {%0,%1,%2,%3}, [%4];" \
                 : "=r"(r0), "=r"(r1), "=r"(r2), "=r"(r3) : "r"(addr))
#define LDMX4(r0, r1, r2, r3, a) \
    asm volatile("ldmatrix.sync.aligned.m8n8.x4.shared.b16 {%0,%1,%2,%3}, [%4];" \
                 : "=r"(r0), "=r"(r1), "=r"(r2), "=r"(r3) : "r"(a))
#define MMA16816(d, a0, a1, a2, a3, b0, b1) \
    asm volatile("mma.sync.aligned.m16n8k16.row.col.f32.bf16.bf16.f32 " \
                 "{%0,%1,%2,%3}, {%4,%5,%6,%7}, {%8,%9}, {%0,%1,%2,%3};" \
                 : "+f"((d)[0]), "+f"((d)[1]), "+f"((d)[2]), "+f"((d)[3]) \
                 : "r"(a0), "r"(a1), "r"(a2), "r"(a3), "r"(b0), "r"(b1))

__device__ __forceinline__ uint32_t pack_bf16(float a, float b) {
    __nv_bfloat162 h = __floats2bfloat162_rn(a, b);
    return *(uint32_t*)&h;
}
// split 8 floats into bf16 hi + residual lo, packed as 4+4 b32
__device__ __forceinline__ void hilo8(const float* v, uint32_t* h, uint32_t* l) {
#pragma unroll
    for (int p = 0; p < 4; p++) {
        __nv_bfloat162 hh = __floats2bfloat162_rn(v[2*p], v[2*p+1]);
        float2 hf = __bfloat1622float2(hh);
        __nv_bfloat162 ll = __floats2bfloat162_rn(v[2*p] - hf.x, v[2*p+1] - hf.y);
        h[p] = *(uint32_t*)&hh;
        l[p] = *(uint32_t*)&ll;
    }
}

// fast exp via FMA poly (avoids MUFU bottleneck; |x| < ~80, rel err ~4e-5)
__device__ __forceinline__ float fexp(float x) {
    const float t = x * 1.4426950408889634f;
    const float n = rintf(t);
    const float r = t - n;
    float p = 0.009618130f;
    p = fmaf(p, r, 0.055504110f);
    p = fmaf(p, r, 0.240226507f);
    p = fmaf(p, r, 0.693147181f);
    p = fmaf(p, r, 1.0f);
    return __int_as_float(__float_as_int(p) + ((int)n << 23));
}

// ============================================================
// transpose: xT[b][n][ci] (bf16) from x[b][ci][n] (fp32)
// ============================================================
__global__ void __launch_bounds__(256) transpose_kernel(
    const float* __restrict__ x, __nv_bfloat16* __restrict__ xT)
{
    __shared__ float t[32][33];
    const int tx = threadIdx.x, ty = threadIdx.y;
    const int n0 = blockIdx.x * 32, ci0 = blockIdx.y * 32, b = blockIdx.z;
#pragma unroll
    for (int j = 0; j < 4; j++)
        t[ty + j * 8][tx] = x[((size_t)b * CC + ci0 + ty + j * 8) * NN + n0 + tx];
    __syncthreads();
#pragma unroll
    for (int j = 0; j < 4; j++) {
        const int n = n0 + ty + j * 8;
        xT[((size_t)b * NN + n) * CC + ci0 + tx] = __float2bfloat16(t[tx][ty + j * 8]);
    }
}

// ============================================================
// weight packing: Wt[t][co][ci] bf16 from w[co][ci][t] fp32
// ============================================================
__global__ void pack_wv_kernel(const float* __restrict__ wv,
                               __nv_bfloat16* __restrict__ Wt)
{
    const int i = blockIdx.x * 256 + threadIdx.x;   // 9*256*256
    const int t = i / (CC * CC);
    const int r = i % (CC * CC);
    const int co = r >> 8, ci = r & 255;
    Wt[i] = __float2bfloat16(wv[((size_t)co * CC + ci) * 9 + t]);
}
__global__ void pack_wqk_kernel(const float* __restrict__ wq,
                                const float* __restrict__ wk,
                                __nv_bfloat16* __restrict__ Wt)
{
    const int i = blockIdx.x * 256 + threadIdx.x;   // 9*64*256
    const int t = i / (64 * CC);
    const int r = i % (64 * CC);
    const int co = r >> 8, ci = r & 255;
    const float v = (co < 32) ? wq[((size_t)co * CC + ci) * 9 + t]
                              : wk[((size_t)(co - 32) * CC + ci) * 9 + t];
    Wt[i] = __float2bfloat16(v);
}

// ============================================================
// qkpack: fp32 [b][d][n] -> bf16 hi/lo [b][n][hi32|lo32]
// tile: 64 n x 32 d per block
// ============================================================
__global__ void __launch_bounds__(256) qkpack_kernel()
{
    __shared__ float t[32][65];
    const int tid = threadIdx.x;
    const int n0 = blockIdx.x * 64;
    const int sel = blockIdx.y;
    const int b = blockIdx.z;
    const float* src = (sel ? g_K : g_Q) + (size_t)b * CQK * NN;
    uint8_t* dst = (uint8_t*)((sel ? g_Khl : g_Qhl) + (size_t)b * NN * 64);

    const int d = tid >> 3, ng = (tid & 7) * 8;
    const float4 f0 = *(const float4*)&src[(size_t)d * NN + n0 + ng];
    const float4 f1 = *(const float4*)&src[(size_t)d * NN + n0 + ng + 4];
    t[d][ng + 0] = f0.x; t[d][ng + 1] = f0.y; t[d][ng + 2] = f0.z; t[d][ng + 3] = f0.w;
    t[d][ng + 4] = f1.x; t[d][ng + 5] = f1.y; t[d][ng + 6] = f1.z; t[d][ng + 7] = f1.w;
    __syncthreads();

    const int n = tid >> 2, dg = (tid & 3) * 8;
    float v[8];
#pragma unroll
    for (int i = 0; i < 8; i++) v[i] = t[dg + i][n];
    uint32_t h[4], l[4];
    hilo8(v, h, l);
    uint8_t* row = dst + (size_t)(n0 + n) * 128;
    *(uint4*)(row + dg * 2)      = make_uint4(h[0], h[1], h[2], h[3]);
    *(uint4*)(row + 64 + dg * 2) = make_uint4(l[0], l[1], l[2], l[3]);
}

// ============================================================
// implicit-GEMM conv3x3 via mma.sync
// MODE 0: bf16 out [b][256][n] (V).  MODE 1: fp32 split q/k [b][32][n].
// ============================================================
template<int COT, int MODE>
__global__ void __launch_bounds__(256) conv_mma_kernel(
    const __nv_bfloat16* __restrict__ xT,
    const __nv_bfloat16* __restrict__ Wt,
    const float* __restrict__ bias0, const float* __restrict__ bias1,
    void* __restrict__ out0, void* __restrict__ out1)
{
    extern __shared__ uint8_t dynsmem[];
    constexpr int COTOT = (MODE == 0) ? 256 : 64;   // Wt rows per tap
    constexpr int MW = COT / 32;     // m warps
    constexpr int NW = 8 / MW;       // n warps
    constexpr int NT = 128 / NW;     // warp n-tile (px)
    constexpr int NB8 = NT / 8;
    constexpr int NBG = NT / 16;

    const int tid = threadIdx.x;
    const int wid = tid >> 5, lid = tid & 31;
    const int wm = wid / NW, wn = wid % NW;
    const int y0 = blockIdx.x * 2;
    const int n0 = y0 * 64;
    const int co0 = blockIdx.y * COT;
    const int b = blockIdx.z;

    const uint32_t sbase = (smem_u32(dynsmem) + 1023) & ~1023u;
    const uint32_t abase = sbase + 33792;

    // zero row at strip slot 256
    if (tid < 32) STS32U(sbase + 32768 + tid * 4, 0u);

    const int frow = lid & 15;
    const int fcb = (lid >> 4) * 16;

    float acc[2][NB8][4];
#pragma unroll
    for (int mt = 0; mt < 2; mt++)
#pragma unroll
        for (int nb = 0; nb < NB8; nb++)
#pragma unroll
            for (int i = 0; i < 4; i++) acc[mt][nb][i] = 0.f;

    // strip staging geometry: thread = one pixel slot (4 rows x 64 px)
    const int spx = tid & 63, sry = tid >> 6;
    const int sy = y0 - 1 + sry;
    const bool srow_ok = (sy >= 0) && (sy < HH);
    const uint8_t* xrow = (const uint8_t*)(xT +
        ((size_t)b * NN + (srow_ok ? sy : 0) * 64 + spx) * CC);

    for (int ci0 = 0; ci0 < CC; ci0 += 64) {
        __syncthreads();   // prior tap's mma done before strip overwrite
        // stage strip: 256 px x 64 ci (128B rows)
#pragma unroll
        for (int j = 0; j < 8; j++) {
            uint4 d = make_uint4(0, 0, 0, 0);
            if (srow_ok) d = *(const uint4*)(xrow + ci0 * 2 + j * 16);
            STS128U(sbase + SWZ((uint32_t)(tid * 128 + j * 16)), d.x, d.y, d.z, d.w);
        }
        for (int tap = 0; tap < 9; tap++) {
            __syncthreads();   // strip ready / prior mma done before A overwrite
            // stage A: COT rows x 64 ci
#pragma unroll
            for (int j = 0; j < COT / 32; j++) {
                const int i = j * 256 + tid;         // uint4 index
                const int row = i >> 3;
                const int cb = (i & 7) * 16;
                const uint8_t* src = (const uint8_t*)Wt +
                    (((size_t)tap * COTOT + co0 + row) * CC + ci0) * 2 + cb;
                const uint4 d = *(const uint4*)src;
                STS128U(abase + SWZ((uint32_t)(row * 128 + cb)), d.x, d.y, d.z, d.w);
            }
            __syncthreads();   // A ready

            // per-lane B row bases for this tap (boundary -> zero row)
            const int dy = tap / 3 - 1, dx = tap % 3 - 1;
            uint32_t brow[NBG];
#pragma unroll
            for (int g = 0; g < NBG; g++) {
                const int pn = wn * NT + g * 16 + frow;
                const int py = pn >> 6, px = pn & 63;
                const int yy = y0 + py + dy;
                const int xx = px + dx;
                const bool ok = (yy >= 0) && (yy < HH) && (xx >= 0) && (xx < WW);
                brow[g] = ok ? (uint32_t)(((py + dy + 1) * 64 + xx) * 128) : 32768u;
            }

#pragma unroll
            for (int ks = 0; ks < 4; ks++) {
                const uint32_t cib = ks * 32 + fcb;
                uint32_t Am[2][4];
#pragma unroll
                for (int mt = 0; mt < 2; mt++)
                    LDMX4(Am[mt][0], Am[mt][1], Am[mt][2], Am[mt][3],
                          abase + SWZ((uint32_t)((wm * 32 + mt * 16 + frow) * 128 + cib)));
                uint32_t Bf[NBG][4];
#pragma unroll
                for (int g = 0; g < NBG; g++)
                    LDMX4(Bf[g][0], Bf[g][1], Bf[g][2], Bf[g][3],
                          sbase + SWZ(brow[g] + cib));
#pragma unroll
                for (int mt = 0; mt < 2; mt++)
#pragma unroll
                    for (int g = 0; g < NBG; g++) {
                        MMA16816(acc[mt][2 * g],     Am[mt][0], Am[mt][1], Am[mt][2], Am[mt][3],
                                 Bf[g][0], Bf[g][2]);
                        MMA16816(acc[mt][2 * g + 1], Am[mt][0], Am[mt][1], Am[mt][2], Am[mt][3],
                                 Bf[g][1], Bf[g][3]);
                    }
            }
        }
    }

    // epilogue
    const int er = lid >> 2, ec = (lid & 3) * 2;
    if (MODE == 0) {
        __nv_bfloat16* ov = (__nv_bfloat16*)out0;
#pragma unroll
        for (int mt = 0; mt < 2; mt++)
#pragma unroll
            for (int h = 0; h < 2; h++) {
                const int co = wm * 32 + mt * 16 + er + h * 8;
                const float bb = bias0[co0 + co];
#pragma unroll
                for (int nb = 0; nb < NB8; nb++) {
                    const int n = n0 + wn * NT + nb * 8 + ec;
                    const uint32_t pk = pack_bf16(acc[mt][nb][h * 2] + bb,
                                                  acc[mt][nb][h * 2 + 1] + bb);
                    *(uint32_t*)&ov[((size_t)b * CC + co0 + co) * NN + n] = pk;
                }
            }
    } else {
#pragma unroll
        for (int mt = 0; mt < 2; mt++)
#pragma unroll
            for (int h = 0; h < 2; h++) {
                const int co = wm * 32 + mt * 16 + er + h * 8;
                float* dst; int d; float bb;
                if (co < 32) { dst = (float*)out0; d = co;      bb = bias0[d]; }
                else         { dst = (float*)out1; d = co - 32; bb = bias1[d]; }
#pragma unroll
                for (int nb = 0; nb < NB8; nb++) {
                    const int n = n0 + wn * NT + nb * 8 + ec;
                    float2 o;
                    o.x = acc[mt][nb][h * 2] + bb;
                    o.y = acc[mt][nb][h * 2 + 1] + bb;
                    *(float2*)&dst[((size_t)b * CQK + d) * NN + n] = o;
                }
            }
    }
}

// ============================================================
// qk_mma: P[b][k][q] = exp(S), S = K.Q^T via bf16 hi/lo 3-chain mma.
// Also accumulates Lpart[b][k][half] = sum over this block's q range.
// Block: k-tile 128 (8 warps x 16 k), q-half 2048 in chunks of 64.
// ============================================================
__global__ void __launch_bounds__(256) qk_mma_kernel()
{
    __shared__ __align__(128) uint8_t sK[128 * 128];   // [k][hi|lo]
    __shared__ __align__(128) uint8_t sQ[64 * 128];    // [q][hi|lo]
    __shared__ __align__(128) uint8_t sP[128 * 128];   // [k][64 q bf16]

    const int tid = threadIdx.x, wid = tid >> 5, lid = tid & 31;
    const int k0 = blockIdx.x * 128;
    const int qh = blockIdx.y;           // q half: [qh*2048, qh*2048+2048)
    const int b  = blockIdx.z;

    const uint32_t kb = smem_u32(sK);
    const uint32_t qb = smem_u32(sQ);
    const uint32_t pb = smem_u32(sP);

    // stage K tile (pure copy: layout already [k][hi|lo])
    {
        const uint8_t* Ks = (const uint8_t*)g_Khl + ((size_t)b * NN + k0) * 128;
        const int r = tid >> 1, seg = (tid & 1) * 64;
#pragma unroll
        for (int j = 0; j < 4; j++) {
            const uint4 d = *(const uint4*)(Ks + (size_t)r * 128 + seg + j * 16);
            STS128U(kb + SWZ((uint32_t)(r * 128 + seg + j * 16)), d.x, d.y, d.z, d.w);
        }
    }

    const uint8_t* Qs = (const uint8_t*)g_Qhl +
                        ((size_t)b * NN + (size_t)qh * (NN / 2)) * 128;
    __nv_bfloat16* Pb = g_P + (size_t)b * NN * NN;

    const int frow = lid & 15, fhc = (lid >> 4) * 16;
    const int er = lid >> 2, ec = (lid & 3) * 2;
    const int sqr = tid >> 2, sqseg = (tid & 3) * 32;
    const int cpr = tid >> 1, cpseg = (tid & 1) * 64;

    float l0 = 0.f, l1 = 0.f;

    for (int cn = 0; cn < NN / 128; cn++) {      // 32 chunks of 64 q
        __syncthreads();   // S1: prev sP->gmem copy done; K staged (1st iter)
        // stage Q chunk (pure copy)
#pragma unroll
        for (int j = 0; j < 2; j++) {
            const uint4 d = *(const uint4*)(Qs + (size_t)(cn * 64 + sqr) * 128
                                            + sqseg + j * 16);
            STS128U(qb + SWZ((uint32_t)(sqr * 128 + sqseg + j * 16)),
                    d.x, d.y, d.z, d.w);
        }
        __syncthreads();   // S2: Q ready

        float sa[8][4];
#pragma unroll
        for (int i = 0; i < 8; i++)
#pragma unroll
            for (int j = 0; j < 4; j++) sa[i][j] = 0.f;

#pragma unroll
        for (int s = 0; s < 2; s++) {
            uint32_t Ah[4], Al[4];
            LDMX4(Ah[0], Ah[1], Ah[2], Ah[3],
                  kb + SWZ((uint32_t)((wid * 16 + frow) * 128 + s * 32 + fhc)));
            LDMX4(Al[0], Al[1], Al[2], Al[3],
                  kb + SWZ((uint32_t)((wid * 16 + frow) * 128 + 64 + s * 32 + fhc)));
#pragma unroll
            for (int qg = 0; qg < 4; qg++) {
                uint32_t Bh[4], Bl[4];
                LDMX4(Bh[0], Bh[1], Bh[2], Bh[3],
                      qb + SWZ((uint32_t)((qg * 16 + frow) * 128 + s * 32 + fhc)));
                LDMX4(Bl[0], Bl[1], Bl[2], Bl[3],
                      qb + SWZ((uint32_t)((qg * 16 + frow) * 128 + 64 + s * 32 + fhc)));
                MMA16816(sa[qg*2+0], Ah[0], Ah[1], Ah[2], Ah[3], Bh[0], Bh[2]);
                MMA16816(sa[qg*2+1], Ah[0], Ah[1], Ah[2], Ah[3], Bh[1], Bh[3]);
                MMA16816(sa[qg*2+0], Ah[0], Ah[1], Ah[2], Ah[3], Bl[0], Bl[2]);
                MMA16816(sa[qg*2+1], Ah[0], Ah[1], Ah[2], Ah[3], Bl[1], Bl[3]);
                MMA16816(sa[qg*2+0], Al[0], Al[1], Al[2], Al[3], Bh[0], Bh[2]);
                MMA16816(sa[qg*2+1], Al[0], Al[1], Al[2], Al[3], Bh[1], Bh[3]);
            }
        }

        // exp, accumulate L, stage P tile
#pragma unroll
        for (int n8 = 0; n8 < 8; n8++) {
            const float e0 = fexp(sa[n8][0]);
            const float e1 = fexp(sa[n8][1]);
            const float e2 = fexp(sa[n8][2]);
            const float e3 = fexp(sa[n8][3]);
            l0 += e0 + e1;
            l1 += e2 + e3;
            const int qq = n8 * 8 + ec;
            STS32U(pb + SWZ((uint32_t)((wid * 16 + er) * 128 + qq * 2)),
                   pack_bf16(e0, e1));
            STS32U(pb + SWZ((uint32_t)((wid * 16 + er + 8) * 128 + qq * 2)),
                   pack_bf16(e2, e3));
        }
        __syncthreads();   // S3: sP complete

        // copy sP -> gmem (coalesced uint4)
        {
            const size_t qc = (size_t)qh * (NN / 2) + (size_t)cn * 64;
            uint8_t* dst = (uint8_t*)(Pb + (size_t)(k0 + cpr) * NN + qc) + cpseg;
#pragma unroll
            for (int j = 0; j < 4; j++) {
                uint32_t a, b2, c, d;
                LDS128U(a, b2, c, d, pb + SWZ((uint32_t)(cpr * 128 + cpseg + j * 16)));
                *(uint4*)(dst + j * 16) = make_uint4(a, b2, c, d);
            }
        }
    }

    // reduce L over the 4 lanes sharing a row, write partials
    l0 += __shfl_xor_sync(0xFFFFFFFF, l0, 1);
    l0 += __shfl_xor_sync(0xFFFFFFFF, l0, 2);
    l1 += __shfl_xor_sync(0xFFFFFFFF, l1, 1);
    l1 += __shfl_xor_sync(0xFFFFFFFF, l1, 2);
    if ((lid & 3) == 0) {
        g_Lpart[((size_t)b * NN + k0 + wid * 16 + er) * 2 + qh]     = l0;
        g_Lpart[((size_t)b * NN + k0 + wid * 16 + er + 8) * 2 + qh] = l1;
    }
}

// ============================================================
// OV via mma.sync: D[c,k] = sum_q V[c,q]*P[k,q]
// Block tile: 128 c x 128 k, q-chunks 64. 8 warps = 4(m) x 2(n),
// warp = 32c x 64k. out = x + gamma * (1/L[k]) * D
// ============================================================
__global__ void __launch_bounds__(256) ov_mma_kernel(
    const float* __restrict__ x, const float* __restrict__ gamma,
    float* __restrict__ out)
{
    __shared__ uint32_t smem_raw[(16384 + 16384 + 128) / 4];
    __shared__ float Lsh[128];

    const int tid = threadIdx.x;
    const int wid = tid >> 5;
    const int lid = tid & 31;
    const int wm = wid >> 1;            // 0..3 : c block of 32
    const int wn = wid & 1;             // 0..1 : k block of 64
    const int k0 = blockIdx.x * 128;
    const int c0 = blockIdx.y * 128;
    const int b  = blockIdx.z;

    const uint32_t abase = (smem_u32(smem_raw) + 127) & ~127u;
    const uint32_t bbase = abase + 16384;

    if (tid < 128) {
        const float2 lp = *(const float2*)&g_Lpart[((size_t)b * NN + k0 + tid) * 2];
        Lsh[tid] = 1.f / (lp.x + lp.y);
    }

    const __nv_bfloat16* Vg = g_Vbf + ((size_t)b * CC + c0) * NN;
    const __nv_bfloat16* Pg = g_P + (size_t)b * NN * NN;

    const int srow = tid >> 1;          // 0..127
    const int qo = (tid & 1) * 32;      // element offset (half row)

    uint4 a_pre[4], b_pre[4];
#pragma unroll
    for (int j = 0; j < 4; j++) {
        a_pre[j] = *(const uint4*)&Vg[(size_t)srow * NN + qo + j * 8];
        b_pre[j] = *(const uint4*)&Pg[(size_t)(k0 + srow) * NN + qo + j * 8];
    }

    float acc[2][8][4];
#pragma unroll
    for (int mt = 0; mt < 2; mt++)
#pragma unroll
        for (int nt = 0; nt < 8; nt++)
#pragma unroll
            for (int i = 0; i < 4; i++) acc[mt][nt][i] = 0.f;

    const int frow = lid & 15;
    const int fcb  = (lid >> 4) * 16;

    for (int chunk = 0; chunk < NN / 64; chunk++) {
        __syncthreads();
#pragma unroll
        for (int j = 0; j < 4; j++) {
            STS128U(abase + SWZ((uint32_t)(srow * 128 + qo * 2 + j * 16)),
                    a_pre[j].x, a_pre[j].y, a_pre[j].z, a_pre[j].w);
            STS128U(bbase + SWZ((uint32_t)(srow * 128 + qo * 2 + j * 16)),
                    b_pre[j].x, b_pre[j].y, b_pre[j].z, b_pre[j].w);
        }
        __syncthreads();

        if (chunk + 1 < NN / 64) {
            const int qc = (chunk + 1) * 64;
#pragma unroll
            for (int j = 0; j < 4; j++) {
                a_pre[j] = *(const uint4*)&Vg[(size_t)srow * NN + qc + qo + j * 8];
                b_pre[j] = *(const uint4*)&Pg[(size_t)(k0 + srow) * NN + qc + qo + j * 8];
            }
        }

#pragma unroll
        for (int ks = 0; ks < 4; ks++) {
            const uint32_t cib = ks * 32 + fcb;
            uint32_t Am[2][4];
#pragma unroll
            for (int mt = 0; mt < 2; mt++)
                LDMX4(Am[mt][0], Am[mt][1], Am[mt][2], Am[mt][3],
                      abase + SWZ((uint32_t)((wm * 32 + mt * 16 + frow) * 128 + cib)));
            uint32_t Bf[4][4];
#pragma unroll
            for (int g = 0; g < 4; g++)
                LDMX4(Bf[g][0], Bf[g][1], Bf[g][2], Bf[g][3],
                      bbase + SWZ((uint32_t)((wn * 64 + g * 16 + frow) * 128 + cib)));
#pragma unroll
            for (int mt = 0; mt < 2; mt++)
#pragma unroll
                for (int g = 0; g < 4; g++) {
                    MMA16816(acc[mt][2 * g],     Am[mt][0], Am[mt][1], Am[mt][2], Am[mt][3],
                             Bf[g][0], Bf[g][2]);
                    MMA16816(acc[mt][2 * g + 1], Am[mt][0], Am[mt][1], Am[mt][2], Am[mt][3],
                             Bf[g][1], Bf[g][3]);
                }
        }
    }

    // epilogue: out = x + g * Linv[k] * D
    const float g = gamma[0];
    const int er = lid >> 2;
    const int ec = (lid & 3) * 2;
#pragma unroll
    for (int mt = 0; mt < 2; mt++) {
#pragma unroll
        for (int nt = 0; nt < 8; nt++) {
            const int kk = wn * 64 + nt * 8 + ec;
            const float l0 = Lsh[kk], l1 = Lsh[kk + 1];
#pragma unroll
            for (int h = 0; h < 2; h++) {
                const int c = c0 + wm * 32 + mt * 16 + er + h * 8;
                const size_t idx = ((size_t)b * CC + c) * NN + k0 + kk;
                const float2 xv = *(const float2*)&x[idx];
                float2 o;
                o.x = xv.x + g * l0 * acc[mt][nt][h * 2 + 0];
                o.y = xv.y + g * l1 * acc[mt][nt][h * 2 + 1];
                *(float2*)&out[idx] = o;
            }
        }
    }
}

// ============================================================
extern "C" void kernel_launch(void* const* d_in, const int* in_sizes, int n_in,
                              void* d_out, int out_size)
{
    const float* x     = (const float*)d_in[0];
    const float* wq    = (const float*)d_in[1];
    const float* bq    = (const float*)d_in[2];
    const float* wk    = (const float*)d_in[3];
    const float* bk    = (const float*)d_in[4];
    const float* wv    = (const float*)d_in[5];
    const float* bv    = (const float*)d_in[6];
    const float* gamma = (const float*)d_in[7];
    float* out = (float*)d_out;

    float *Qp, *Kp;
    __nv_bfloat16 *Vbp, *xTp, *WtVp, *WtQKp;
    cudaGetSymbolAddress((void**)&Qp, g_Q);
    cudaGetSymbolAddress((void**)&Kp, g_K);
    cudaGetSymbolAddress((void**)&Vbp, g_Vbf);
    cudaGetSymbolAddress((void**)&xTp, g_xT);
    cudaGetSymbolAddress((void**)&WtVp, g_WtV);
    cudaGetSymbolAddress((void**)&WtQKp, g_WtQK);

    static int attr_set = 0;
    const int SMV = 1024 + 33792 + 16384;   // 51200
    const int SMQK = 1024 + 33792 + 8192;   // 43008
    if (!attr_set) {
        cudaFuncSetAttribute(conv_mma_kernel<128, 0>,
                             cudaFuncAttributeMaxDynamicSharedMemorySize, SMV);
        cudaFuncSetAttribute(conv_mma_kernel<64, 1>,
                             cudaFuncAttributeMaxDynamicSharedMemorySize, SMQK);
        attr_set = 1;
    }

    transpose_kernel<<<dim3(NN / 32, CC / 32, BB), dim3(32, 8)>>>(x, xTp);
    pack_wv_kernel<<<(9 * CC * CC) / 256, 256>>>(wv, WtVp);
    pack_wqk_kernel<<<(9 * 64 * CC) / 256, 256>>>(wq, wk, WtQKp);

    conv_mma_kernel<128, 0><<<dim3(32, 2, BB), 256, SMV>>>(
        xTp, WtVp, bv, nullptr, Vbp, nullptr);
    conv_mma_kernel<64, 1><<<dim3(32, 1, BB), 256, SMQK>>>(
        xTp, WtQKp, bq, bk, Qp, Kp);

    qkpack_kernel<<<dim3(NN / 64, 2, BB), 256>>>();
    qk_mma_kernel<<<dim3(NN / 128, 2, BB), 256>>>();
    ov_mma_kernel<<<dim3(NN / 128, CC / 128, BB), 256>>>(x, gamma, out);
}

// round 12
// speedup vs baseline: 7.4902x; 1.0434x over previous
#include <cuda_runtime.h>
#include <cuda_bf16.h>
#include <stdint.h>
#include <math.h>

#define BB 4
#define CC 256
#define HH 64
#define WW 64
#define NN (HH*WW)      // 4096
#define CQK 32

// ---- scratch (static device globals; no allocation) ----
__device__ float g_Q[BB*CQK*NN];                    // 2 MB   [b][d][n] (conv out)
__device__ float g_K[BB*CQK*NN];                    // 2 MB   [b][d][n] (conv out)
__device__ __nv_bfloat16 g_Qhl[BB*NN*64];           // 2 MB   [b][n][hi d0..31 | lo d0..31]
__device__ __nv_bfloat16 g_Khl[BB*NN*64];           // 2 MB   [b][n][hi | lo]
__device__ __nv_bfloat16 g_Vbf[BB*CC*NN];           // 8 MB   [b][c][n]
__device__ __nv_bfloat16 g_P[(size_t)BB*NN*NN];     // 128 MB P=exp(S^T): [b][k][q]
__device__ float g_Lpart[BB*NN*2];                  // partial col sums (per k, q-half)
__device__ __nv_bfloat16 g_xT[(size_t)BB*NN*CC];    // 8 MB   xT: [b][n][ci]
__device__ __nv_bfloat16 g_WtV[9*CC*CC];            // 1.1 MB [t][co][ci]
__device__ __nv_bfloat16 g_WtQK[9*64*CC];           // 288 KB [t][co(q0-31,k32-63)][ci]

// ============================================================
// helpers
// ============================================================
__device__ __forceinline__ uint32_t smem_u32(const void* p) {
    uint32_t a;
    asm("{ .reg .u64 t; cvta.to.shared.u64 t, %1; cvt.u32.u64 %0, t; }"
        : "=r"(a) : "l"(p));
    return a;
}
#define SWZ(x) ((x) ^ (((x) >> 3) & 0x70))
#define STS128U(addr, a, b, c, d) \
    asm volatile("st.shared.v4.b32 [%0], {%1, %2, %3, %4};" \
                 :: "r"(addr), "r"(a), "r"(b), "r"(c), "r"(d) : "memory")
#define STS32U(addr, a) \
    asm volatile("st.shared.b32 [%0], %1;" :: "r"(addr), "r"(a) : "memory")
#define LDS128U(r0, r1, r2, r3, addr) \
    asm volatile("ld.shared.v4.b32 {%0,%1,%2,%3}, [%4];" \
                 : "=r"(r0), "=r"(r1), "=r"(r2), "=r"(r3) : "r"(addr))
#define LDMX4(r0, r1, r2, r3, a) \
    asm volatile("ldmatrix.sync.aligned.m8n8.x4.shared.b16 {%0,%1,%2,%3}, [%4];" \
                 : "=r"(r0), "=r"(r1), "=r"(r2), "=r"(r3) : "r"(a))
#define MMA16816(d, a0, a1, a2, a3, b0, b1) \
    asm volatile("mma.sync.aligned.m16n8k16.row.col.f32.bf16.bf16.f32 " \
                 "{%0,%1,%2,%3}, {%4,%5,%6,%7}, {%8,%9}, {%0,%1,%2,%3};" \
                 : "+f"((d)[0]), "+f"((d)[1]), "+f"((d)[2]), "+f"((d)[3]) \
                 : "r"(a0), "r"(a1), "r"(a2), "r"(a3), "r"(b0), "r"(b1))

__device__ __forceinline__ uint32_t pack_bf16(float a, float b) {
    __nv_bfloat162 h = __floats2bfloat162_rn(a, b);
    return *(uint32_t*)&h;
}
// split 8 floats into bf16 hi + residual lo, packed as 4+4 b32
__device__ __forceinline__ void hilo8(const float* v, uint32_t* h, uint32_t* l) {
#pragma unroll
    for (int p = 0; p < 4; p++) {
        __nv_bfloat162 hh = __floats2bfloat162_rn(v[2*p], v[2*p+1]);
        float2 hf = __bfloat1622float2(hh);
        __nv_bfloat162 ll = __floats2bfloat162_rn(v[2*p] - hf.x, v[2*p+1] - hf.y);
        h[p] = *(uint32_t*)&hh;
        l[p] = *(uint32_t*)&ll;
    }
}

// fast exp via FMA poly (avoids MUFU bottleneck; |x| < ~80, rel err ~4e-5)
__device__ __forceinline__ float fexp(float x) {
    const float t = x * 1.4426950408889634f;
    const float n = rintf(t);
    const float r = t - n;
    float p = 0.009618130f;
    p = fmaf(p, r, 0.055504110f);
    p = fmaf(p, r, 0.240226507f);
    p = fmaf(p, r, 0.693147181f);
    p = fmaf(p, r, 1.0f);
    return __int_as_float(__float_as_int(p) + ((int)n << 23));
}

// ============================================================
// transpose: xT[b][n][ci] (bf16) from x[b][ci][n] (fp32)
// ============================================================
__global__ void __launch_bounds__(256) transpose_kernel(
    const float* __restrict__ x, __nv_bfloat16* __restrict__ xT)
{
    __shared__ float t[32][33];
    const int tx = threadIdx.x, ty = threadIdx.y;
    const int n0 = blockIdx.x * 32, ci0 = blockIdx.y * 32, b = blockIdx.z;
#pragma unroll
    for (int j = 0; j < 4; j++)
        t[ty + j * 8][tx] = x[((size_t)b * CC + ci0 + ty + j * 8) * NN + n0 + tx];
    __syncthreads();
#pragma unroll
    for (int j = 0; j < 4; j++) {
        const int n = n0 + ty + j * 8;
        xT[((size_t)b * NN + n) * CC + ci0 + tx] = __float2bfloat16(t[tx][ty + j * 8]);
    }
}

// ============================================================
// weight packing: Wt[t][co][ci] bf16 from w[co][ci][t] fp32
// ============================================================
__global__ void pack_wv_kernel(const float* __restrict__ wv,
                               __nv_bfloat16* __restrict__ Wt)
{
    const int i = blockIdx.x * 256 + threadIdx.x;   // 9*256*256
    const int t = i / (CC * CC);
    const int r = i % (CC * CC);
    const int co = r >> 8, ci = r & 255;
    Wt[i] = __float2bfloat16(wv[((size_t)co * CC + ci) * 9 + t]);
}
__global__ void pack_wqk_kernel(const float* __restrict__ wq,
                                const float* __restrict__ wk,
                                __nv_bfloat16* __restrict__ Wt)
{
    const int i = blockIdx.x * 256 + threadIdx.x;   // 9*64*256
    const int t = i / (64 * CC);
    const int r = i % (64 * CC);
    const int co = r >> 8, ci = r & 255;
    const float v = (co < 32) ? wq[((size_t)co * CC + ci) * 9 + t]
                              : wk[((size_t)(co - 32) * CC + ci) * 9 + t];
    Wt[i] = __float2bfloat16(v);
}

// ============================================================
// qkpack: fp32 [b][d][n] -> bf16 hi/lo [b][n][hi32|lo32]
// ============================================================
__global__ void __launch_bounds__(256) qkpack_kernel()
{
    __shared__ float t[32][65];
    const int tid = threadIdx.x;
    const int n0 = blockIdx.x * 64;
    const int sel = blockIdx.y;
    const int b = blockIdx.z;
    const float* src = (sel ? g_K : g_Q) + (size_t)b * CQK * NN;
    uint8_t* dst = (uint8_t*)((sel ? g_Khl : g_Qhl) + (size_t)b * NN * 64);

    const int d = tid >> 3, ng = (tid & 7) * 8;
    const float4 f0 = *(const float4*)&src[(size_t)d * NN + n0 + ng];
    const float4 f1 = *(const float4*)&src[(size_t)d * NN + n0 + ng + 4];
    t[d][ng + 0] = f0.x; t[d][ng + 1] = f0.y; t[d][ng + 2] = f0.z; t[d][ng + 3] = f0.w;
    t[d][ng + 4] = f1.x; t[d][ng + 5] = f1.y; t[d][ng + 6] = f1.z; t[d][ng + 7] = f1.w;
    __syncthreads();

    const int n = tid >> 2, dg = (tid & 3) * 8;
    float v[8];
#pragma unroll
    for (int i = 0; i < 8; i++) v[i] = t[dg + i][n];
    uint32_t h[4], l[4];
    hilo8(v, h, l);
    uint8_t* row = dst + (size_t)(n0 + n) * 128;
    *(uint4*)(row + dg * 2)      = make_uint4(h[0], h[1], h[2], h[3]);
    *(uint4*)(row + 64 + dg * 2) = make_uint4(l[0], l[1], l[2], l[3]);
}

// ============================================================
// implicit-GEMM conv3x3 via mma.sync, double-buffered A staging
// MODE 0: bf16 out [b][256][n] (V).  MODE 1: fp32 split q/k [b][32][n].
// ============================================================
template<int COT, int MODE>
__global__ void __launch_bounds__(256) conv_mma_kernel(
    const __nv_bfloat16* __restrict__ xT,
    const __nv_bfloat16* __restrict__ Wt,
    const float* __restrict__ bias0, const float* __restrict__ bias1,
    void* __restrict__ out0, void* __restrict__ out1)
{
    extern __shared__ uint8_t dynsmem[];
    constexpr int COTOT = (MODE == 0) ? 256 : 64;   // Wt rows per tap
    constexpr int MW = COT / 32;     // m warps
    constexpr int NW = 8 / MW;       // n warps
    constexpr int NT = 128 / NW;     // warp n-tile (px)
    constexpr int NB8 = NT / 8;
    constexpr int NBG = NT / 16;

    const int tid = threadIdx.x;
    const int wid = tid >> 5, lid = tid & 31;
    const int wm = wid / NW, wn = wid % NW;
    const int y0 = blockIdx.x * 2;
    const int n0 = y0 * 64;
    const int co0 = blockIdx.y * COT;
    const int b = blockIdx.z;

    const uint32_t sbase = (smem_u32(dynsmem) + 1023) & ~1023u;
    const uint32_t abase0 = sbase + 33792;
    const uint32_t abase1 = abase0 + COT * 128;

    // zero row at strip slot 256
    if (tid < 32) STS32U(sbase + 32768 + tid * 4, 0u);

    const int frow = lid & 15;
    const int fcb = (lid >> 4) * 16;

    float acc[2][NB8][4];
#pragma unroll
    for (int mt = 0; mt < 2; mt++)
#pragma unroll
        for (int nb = 0; nb < NB8; nb++)
#pragma unroll
            for (int i = 0; i < 4; i++) acc[mt][nb][i] = 0.f;

    // strip staging geometry: thread = one pixel slot (4 rows x 64 px)
    const int spx = tid & 63, sry = tid >> 6;
    const int sy = y0 - 1 + sry;
    const bool srow_ok = (sy >= 0) && (sy < HH);
    const uint8_t* xrow = (const uint8_t*)(xT +
        ((size_t)b * NN + (srow_ok ? sy : 0) * 64 + spx) * CC);

    auto stage_a = [&](int tap, int ci0, uint32_t ab) {
#pragma unroll
        for (int j = 0; j < COT / 32; j++) {
            const int i = j * 256 + tid;         // uint4 index
            const int row = i >> 3;
            const int cb = (i & 7) * 16;
            const uint8_t* src = (const uint8_t*)Wt +
                (((size_t)tap * COTOT + co0 + row) * CC + ci0) * 2 + cb;
            const uint4 d = *(const uint4*)src;
            STS128U(ab + SWZ((uint32_t)(row * 128 + cb)), d.x, d.y, d.z, d.w);
        }
    };

    for (int ci0 = 0; ci0 < CC; ci0 += 64) {
        // stage strip: 256 px x 64 ci (128B rows). Safe: last tap's sync of
        // previous chunk guarantees all mma reads of strip completed.
#pragma unroll
        for (int j = 0; j < 8; j++) {
            uint4 d = make_uint4(0, 0, 0, 0);
            if (srow_ok) d = *(const uint4*)(xrow + ci0 * 2 + j * 16);
            STS128U(sbase + SWZ((uint32_t)(tid * 128 + j * 16)), d.x, d.y, d.z, d.w);
        }
        stage_a(0, ci0, abase0);
        __syncthreads();   // strip + A(tap0) ready (also covers zero-row, 1st iter)

        for (int tap = 0; tap < 9; tap++) {
            // stage next tap's A into the other buffer (overlaps mma below)
            if (tap < 8) stage_a(tap + 1, ci0, (tap & 1) ? abase0 : abase1);
            const uint32_t ab = (tap & 1) ? abase1 : abase0;

            // per-lane B row bases for this tap (boundary -> zero row)
            const int dy = tap / 3 - 1, dx = tap % 3 - 1;
            uint32_t brow[NBG];
#pragma unroll
            for (int g = 0; g < NBG; g++) {
                const int pn = wn * NT + g * 16 + frow;
                const int py = pn >> 6, px = pn & 63;
                const int yy = y0 + py + dy;
                const int xx = px + dx;
                const bool ok = (yy >= 0) && (yy < HH) && (xx >= 0) && (xx < WW);
                brow[g] = ok ? (uint32_t)(((py + dy + 1) * 64 + xx) * 128) : 32768u;
            }

#pragma unroll
            for (int ks = 0; ks < 4; ks++) {
                const uint32_t cib = ks * 32 + fcb;
                uint32_t Am[2][4];
#pragma unroll
                for (int mt = 0; mt < 2; mt++)
                    LDMX4(Am[mt][0], Am[mt][1], Am[mt][2], Am[mt][3],
                          ab + SWZ((uint32_t)((wm * 32 + mt * 16 + frow) * 128 + cib)));
                uint32_t Bf[NBG][4];
#pragma unroll
                for (int g = 0; g < NBG; g++)
                    LDMX4(Bf[g][0], Bf[g][1], Bf[g][2], Bf[g][3],
                          sbase + SWZ(brow[g] + cib));
#pragma unroll
                for (int mt = 0; mt < 2; mt++)
#pragma unroll
                    for (int g = 0; g < NBG; g++) {
                        MMA16816(acc[mt][2 * g],     Am[mt][0], Am[mt][1], Am[mt][2], Am[mt][3],
                                 Bf[g][0], Bf[g][2]);
                        MMA16816(acc[mt][2 * g + 1], Am[mt][0], Am[mt][1], Am[mt][2], Am[mt][3],
                                 Bf[g][1], Bf[g][3]);
                    }
            }
            __syncthreads();   // A(tap+1) ready; mma(tap) done before buf reuse
        }
    }

    // epilogue
    const int er = lid >> 2, ec = (lid & 3) * 2;
    if (MODE == 0) {
        __nv_bfloat16* ov = (__nv_bfloat16*)out0;
#pragma unroll
        for (int mt = 0; mt < 2; mt++)
#pragma unroll
            for (int h = 0; h < 2; h++) {
                const int co = wm * 32 + mt * 16 + er + h * 8;
                const float bb = bias0[co0 + co];
#pragma unroll
                for (int nb = 0; nb < NB8; nb++) {
                    const int n = n0 + wn * NT + nb * 8 + ec;
                    const uint32_t pk = pack_bf16(acc[mt][nb][h * 2] + bb,
                                                  acc[mt][nb][h * 2 + 1] + bb);
                    *(uint32_t*)&ov[((size_t)b * CC + co0 + co) * NN + n] = pk;
                }
            }
    } else {
#pragma unroll
        for (int mt = 0; mt < 2; mt++)
#pragma unroll
            for (int h = 0; h < 2; h++) {
                const int co = wm * 32 + mt * 16 + er + h * 8;
                float* dst; int d; float bb;
                if (co < 32) { dst = (float*)out0; d = co;      bb = bias0[d]; }
                else         { dst = (float*)out1; d = co - 32; bb = bias1[d]; }
#pragma unroll
                for (int nb = 0; nb < NB8; nb++) {
                    const int n = n0 + wn * NT + nb * 8 + ec;
                    float2 o;
                    o.x = acc[mt][nb][h * 2] + bb;
                    o.y = acc[mt][nb][h * 2 + 1] + bb;
                    *(float2*)&dst[((size_t)b * CQK + d) * NN + n] = o;
                }
            }
    }
}

// ============================================================
// qk_mma: P[b][k][q] = exp(S), S = K.Q^T via bf16 hi/lo 3-chain mma.
// Double-buffered sQ/sP, 1 sync per chunk.
// Block: k-tile 128 (8 warps x 16 k), q-half 2048 in chunks of 64.
// ============================================================
__global__ void __launch_bounds__(256) qk_mma_kernel()
{
    extern __shared__ uint8_t dynq[];
    const uint32_t kb  = (smem_u32(dynq) + 1023) & ~1023u;
    const uint32_t qb0 = kb + 16384;
    const uint32_t qb1 = qb0 + 8192;
    const uint32_t pb0 = qb1 + 8192;
    const uint32_t pb1 = pb0 + 16384;

    const int tid = threadIdx.x, wid = tid >> 5, lid = tid & 31;
    const int k0 = blockIdx.x * 128;
    const int qh = blockIdx.y;           // q half: [qh*2048, qh*2048+2048)
    const int b  = blockIdx.z;

    // stage K tile (pure copy: layout already [k][hi|lo])
    {
        const uint8_t* Ks = (const uint8_t*)g_Khl + ((size_t)b * NN + k0) * 128;
        const int r = tid >> 1, seg = (tid & 1) * 64;
#pragma unroll
        for (int j = 0; j < 4; j++) {
            const uint4 d = *(const uint4*)(Ks + (size_t)r * 128 + seg + j * 16);
            STS128U(kb + SWZ((uint32_t)(r * 128 + seg + j * 16)), d.x, d.y, d.z, d.w);
        }
    }

    const uint8_t* Qs = (const uint8_t*)g_Qhl +
                        ((size_t)b * NN + (size_t)qh * (NN / 2)) * 128;
    __nv_bfloat16* Pb = g_P + (size_t)b * NN * NN;

    const int frow = lid & 15, fhc = (lid >> 4) * 16;
    const int er = lid >> 2, ec = (lid & 3) * 2;
    const int sqr = tid >> 2, sqseg = (tid & 3) * 32;
    const int cpr = tid >> 1, cpseg = (tid & 1) * 64;

    float l0 = 0.f, l1 = 0.f;

    // prefetch Q chunk 0 into regs
    uint4 qpre[2];
#pragma unroll
    for (int j = 0; j < 2; j++)
        qpre[j] = *(const uint4*)(Qs + (size_t)sqr * 128 + sqseg + j * 16);

    for (int cn = 0; cn < NN / 128; cn++) {      // 32 chunks of 64 q
        const uint32_t qb = (cn & 1) ? qb1 : qb0;
        const uint32_t pb = (cn & 1) ? pb1 : pb0;

        // store this chunk's Q from regs; prefetch next
#pragma unroll
        for (int j = 0; j < 2; j++)
            STS128U(qb + SWZ((uint32_t)(sqr * 128 + sqseg + j * 16)),
                    qpre[j].x, qpre[j].y, qpre[j].z, qpre[j].w);
        if (cn + 1 < NN / 128) {
#pragma unroll
            for (int j = 0; j < 2; j++)
                qpre[j] = *(const uint4*)(Qs + (size_t)((cn + 1) * 64 + sqr) * 128
                                          + sqseg + j * 16);
        }
        __syncthreads();   // qbuf[cn] ready; pbuf[cn-1] exp-stores complete

        // copy out previous chunk's P tile (coalesced uint4)
        if (cn > 0) {
            const uint32_t pprev = (cn & 1) ? pb0 : pb1;
            const size_t qc = (size_t)qh * (NN / 2) + (size_t)(cn - 1) * 64;
            uint8_t* dst = (uint8_t*)(Pb + (size_t)(k0 + cpr) * NN + qc) + cpseg;
#pragma unroll
            for (int j = 0; j < 4; j++) {
                uint32_t a, b2, c, d;
                LDS128U(a, b2, c, d, pprev + SWZ((uint32_t)(cpr * 128 + cpseg + j * 16)));
                *(uint4*)(dst + j * 16) = make_uint4(a, b2, c, d);
            }
        }

        float sa[8][4];
#pragma unroll
        for (int i = 0; i < 8; i++)
#pragma unroll
            for (int j = 0; j < 4; j++) sa[i][j] = 0.f;

#pragma unroll
        for (int s = 0; s < 2; s++) {
            uint32_t Ah[4], Al[4];
            LDMX4(Ah[0], Ah[1], Ah[2], Ah[3],
                  kb + SWZ((uint32_t)((wid * 16 + frow) * 128 + s * 32 + fhc)));
            LDMX4(Al[0], Al[1], Al[2], Al[3],
                  kb + SWZ((uint32_t)((wid * 16 + frow) * 128 + 64 + s * 32 + fhc)));
#pragma unroll
            for (int qg = 0; qg < 4; qg++) {
                uint32_t Bh[4], Bl[4];
                LDMX4(Bh[0], Bh[1], Bh[2], Bh[3],
                      qb + SWZ((uint32_t)((qg * 16 + frow) * 128 + s * 32 + fhc)));
                LDMX4(Bl[0], Bl[1], Bl[2], Bl[3],
                      qb + SWZ((uint32_t)((qg * 16 + frow) * 128 + 64 + s * 32 + fhc)));
                MMA16816(sa[qg*2+0], Ah[0], Ah[1], Ah[2], Ah[3], Bh[0], Bh[2]);
                MMA16816(sa[qg*2+1], Ah[0], Ah[1], Ah[2], Ah[3], Bh[1], Bh[3]);
                MMA16816(sa[qg*2+0], Ah[0], Ah[1], Ah[2], Ah[3], Bl[0], Bl[2]);
                MMA16816(sa[qg*2+1], Ah[0], Ah[1], Ah[2], Ah[3], Bl[1], Bl[3]);
                MMA16816(sa[qg*2+0], Al[0], Al[1], Al[2], Al[3], Bh[0], Bh[2]);
                MMA16816(sa[qg*2+1], Al[0], Al[1], Al[2], Al[3], Bh[1], Bh[3]);
            }
        }

        // exp, accumulate L, stage P tile into pbuf[cn&1]
#pragma unroll
        for (int n8 = 0; n8 < 8; n8++) {
            const float e0 = fexp(sa[n8][0]);
            const float e1 = fexp(sa[n8][1]);
            const float e2 = fexp(sa[n8][2]);
            const float e3 = fexp(sa[n8][3]);
            l0 += e0 + e1;
            l1 += e2 + e3;
            const int qq = n8 * 8 + ec;
            STS32U(pb + SWZ((uint32_t)((wid * 16 + er) * 128 + qq * 2)),
                   pack_bf16(e0, e1));
            STS32U(pb + SWZ((uint32_t)((wid * 16 + er + 8) * 128 + qq * 2)),
                   pack_bf16(e2, e3));
        }
    }

    __syncthreads();   // last pbuf complete
    {
        const int cn = NN / 128 - 1;
        const uint32_t plast = (cn & 1) ? pb1 : pb0;
        const size_t qc = (size_t)qh * (NN / 2) + (size_t)cn * 64;
        uint8_t* dst = (uint8_t*)(Pb + (size_t)(k0 + cpr) * NN + qc) + cpseg;
#pragma unroll
        for (int j = 0; j < 4; j++) {
            uint32_t a, b2, c, d;
            LDS128U(a, b2, c, d, plast + SWZ((uint32_t)(cpr * 128 + cpseg + j * 16)));
            *(uint4*)(dst + j * 16) = make_uint4(a, b2, c, d);
        }
    }

    // reduce L over the 4 lanes sharing a row, write partials
    l0 += __shfl_xor_sync(0xFFFFFFFF, l0, 1);
    l0 += __shfl_xor_sync(0xFFFFFFFF, l0, 2);
    l1 += __shfl_xor_sync(0xFFFFFFFF, l1, 1);
    l1 += __shfl_xor_sync(0xFFFFFFFF, l1, 2);
    if ((lid & 3) == 0) {
        g_Lpart[((size_t)b * NN + k0 + wid * 16 + er) * 2 + qh]     = l0;
        g_Lpart[((size_t)b * NN + k0 + wid * 16 + er + 8) * 2 + qh] = l1;
    }
}

// ============================================================
// OV via mma.sync: D[c,k] = sum_q V[c,q]*P[k,q]
// Double-buffered A/B tiles, 1 sync per chunk.
// Block tile: 128 c x 128 k, q-chunks 64. 8 warps = 4(m) x 2(n).
// out = x + gamma * (1/L[k]) * D
// ============================================================
__global__ void __launch_bounds__(256) ov_mma_kernel(
    const float* __restrict__ x, const float* __restrict__ gamma,
    float* __restrict__ out)
{
    extern __shared__ uint8_t dyno[];
    __shared__ float Lsh[128];

    const uint32_t ab0 = (smem_u32(dyno) + 1023) & ~1023u;
    const uint32_t ab1 = ab0 + 16384;
    const uint32_t bb0 = ab1 + 16384;
    const uint32_t bb1 = bb0 + 16384;

    const int tid = threadIdx.x;
    const int wid = tid >> 5;
    const int lid = tid & 31;
    const int wm = wid >> 1;            // 0..3 : c block of 32
    const int wn = wid & 1;             // 0..1 : k block of 64
    const int k0 = blockIdx.x * 128;
    const int c0 = blockIdx.y * 128;
    const int b  = blockIdx.z;

    if (tid < 128) {
        const float2 lp = *(const float2*)&g_Lpart[((size_t)b * NN + k0 + tid) * 2];
        Lsh[tid] = 1.f / (lp.x + lp.y);
    }

    const __nv_bfloat16* Vg = g_Vbf + ((size_t)b * CC + c0) * NN;
    const __nv_bfloat16* Pg = g_P + (size_t)b * NN * NN;

    const int srow = tid >> 1;          // 0..127
    const int qo = (tid & 1) * 32;      // element offset (half row)

    uint4 a_pre[4], b_pre[4];
#pragma unroll
    for (int j = 0; j < 4; j++) {
        a_pre[j] = *(const uint4*)&Vg[(size_t)srow * NN + qo + j * 8];
        b_pre[j] = *(const uint4*)&Pg[(size_t)(k0 + srow) * NN + qo + j * 8];
    }

    float acc[2][8][4];
#pragma unroll
    for (int mt = 0; mt < 2; mt++)
#pragma unroll
        for (int nt = 0; nt < 8; nt++)
#pragma unroll
            for (int i = 0; i < 4; i++) acc[mt][nt][i] = 0.f;

    const int frow = lid & 15;
    const int fcb  = (lid >> 4) * 16;

    for (int chunk = 0; chunk < NN / 64; chunk++) {
        const uint32_t abase = (chunk & 1) ? ab1 : ab0;
        const uint32_t bbase = (chunk & 1) ? bb1 : bb0;

        // store this chunk from regs, prefetch next chunk
#pragma unroll
        for (int j = 0; j < 4; j++) {
            STS128U(abase + SWZ((uint32_t)(srow * 128 + qo * 2 + j * 16)),
                    a_pre[j].x, a_pre[j].y, a_pre[j].z, a_pre[j].w);
            STS128U(bbase + SWZ((uint32_t)(srow * 128 + qo * 2 + j * 16)),
                    b_pre[j].x, b_pre[j].y, b_pre[j].z, b_pre[j].w);
        }
        if (chunk + 1 < NN / 64) {
            const int qc = (chunk + 1) * 64;
#pragma unroll
            for (int j = 0; j < 4; j++) {
                a_pre[j] = *(const uint4*)&Vg[(size_t)srow * NN + qc + qo + j * 8];
                b_pre[j] = *(const uint4*)&Pg[(size_t)(k0 + srow) * NN + qc + qo + j * 8];
            }
        }
        __syncthreads();   // buf[chunk] ready (and mma[chunk-2] long done)

#pragma unroll
        for (int ks = 0; ks < 4; ks++) {
            const uint32_t cib = ks * 32 + fcb;
            uint32_t Am[2][4];
#pragma unroll
            for (int mt = 0; mt < 2; mt++)
                LDMX4(Am[mt][0], Am[mt][1], Am[mt][2], Am[mt][3],
                      abase + SWZ((uint32_t)((wm * 32 + mt * 16 + frow) * 128 + cib)));
            uint32_t Bf[4][4];
#pragma unroll
            for (int g = 0; g < 4; g++)
                LDMX4(Bf[g][0], Bf[g][1], Bf[g][2], Bf[g][3],
                      bbase + SWZ((uint32_t)((wn * 64 + g * 16 + frow) * 128 + cib)));
#pragma unroll
            for (int mt = 0; mt < 2; mt++)
#pragma unroll
                for (int g = 0; g < 4; g++) {
                    MMA16816(acc[mt][2 * g],     Am[mt][0], Am[mt][1], Am[mt][2], Am[mt][3],
                             Bf[g][0], Bf[g][2]);
                    MMA16816(acc[mt][2 * g + 1], Am[mt][0], Am[mt][1], Am[mt][2], Am[mt][3],
                             Bf[g][1], Bf[g][3]);
                }
        }
    }

    // epilogue: out = x + g * Linv[k] * D
    const float g = gamma[0];
    const int er = lid >> 2;
    const int ec = (lid & 3) * 2;
#pragma unroll
    for (int mt = 0; mt < 2; mt++) {
#pragma unroll
        for (int nt = 0; nt < 8; nt++) {
            const int kk = wn * 64 + nt * 8 + ec;
            const float l0 = Lsh[kk], l1 = Lsh[kk + 1];
#pragma unroll
            for (int h = 0; h < 2; h++) {
                const int c = c0 + wm * 32 + mt * 16 + er + h * 8;
                const size_t idx = ((size_t)b * CC + c) * NN + k0 + kk;
                const float2 xv = *(const float2*)&x[idx];
                float2 o;
                o.x = xv.x + g * l0 * acc[mt][nt][h * 2 + 0];
                o.y = xv.y + g * l1 * acc[mt][nt][h * 2 + 1];
                *(float2*)&out[idx] = o;
            }
        }
    }
}

// ============================================================
extern "C" void kernel_launch(void* const* d_in, const int* in_sizes, int n_in,
                              void* d_out, int out_size)
{
    const float* x     = (const float*)d_in[0];
    const float* wq    = (const float*)d_in[1];
    const float* bq    = (const float*)d_in[2];
    const float* wk    = (const float*)d_in[3];
    const float* bk    = (const float*)d_in[4];
    const float* wv    = (const float*)d_in[5];
    const float* bv    = (const float*)d_in[6];
    const float* gamma = (const float*)d_in[7];
    float* out = (float*)d_out;

    float *Qp, *Kp;
    __nv_bfloat16 *Vbp, *xTp, *WtVp, *WtQKp;
    cudaGetSymbolAddress((void**)&Qp, g_Q);
    cudaGetSymbolAddress((void**)&Kp, g_K);
    cudaGetSymbolAddress((void**)&Vbp, g_Vbf);
    cudaGetSymbolAddress((void**)&xTp, g_xT);
    cudaGetSymbolAddress((void**)&WtVp, g_WtV);
    cudaGetSymbolAddress((void**)&WtQKp, g_WtQK);

    static int attr_set = 0;
    const int SMV  = 1024 + 33792 + 2 * 16384;   // 67584
    const int SMQK = 1024 + 33792 + 2 * 8192;    // 51200
    const int SMQM = 1024 + 16384 + 2 * 8192 + 2 * 16384;  // 66560
    const int SMOV = 1024 + 4 * 16384;           // 66560
    if (!attr_set) {
        cudaFuncSetAttribute(conv_mma_kernel<128, 0>,
                             cudaFuncAttributeMaxDynamicSharedMemorySize, SMV);
        cudaFuncSetAttribute(conv_mma_kernel<64, 1>,
                             cudaFuncAttributeMaxDynamicSharedMemorySize, SMQK);
        cudaFuncSetAttribute(qk_mma_kernel,
                             cudaFuncAttributeMaxDynamicSharedMemorySize, SMQM);
        cudaFuncSetAttribute(ov_mma_kernel,
                             cudaFuncAttributeMaxDynamicSharedMemorySize, SMOV);
        attr_set = 1;
    }

    transpose_kernel<<<dim3(NN / 32, CC / 32, BB), dim3(32, 8)>>>(x, xTp);
    pack_wv_kernel<<<(9 * CC * CC) / 256, 256>>>(wv, WtVp);
    pack_wqk_kernel<<<(9 * 64 * CC) / 256, 256>>>(wq, wk, WtQKp);

    conv_mma_kernel<128, 0><<<dim3(32, 2, BB), 256, SMV>>>(
        xTp, WtVp, bv, nullptr, Vbp, nullptr);
    conv_mma_kernel<64, 1><<<dim3(32, 1, BB), 256, SMQK>>>(
        xTp, WtQKp, bq, bk, Qp, Kp);

    qkpack_kernel<<<dim3(NN / 64, 2, BB), 256>>>();
    qk_mma_kernel<<<dim3(NN / 128, 2, BB), 256, SMQM>>>();
    ov_mma_kernel<<<dim3(NN / 128, CC / 128, BB), 256, SMOV>>>(x, gamma, out);
}